// round 13
// baseline (speedup 1.0000x reference)
#include <cuda_runtime.h>
#include <cuda_fp16.h>
#include <cstdint>

#define B_ 16
#define S_ 2048
#define H_ 512
#define W_ 4
#define L_ 2
#define SP_ (S_ + 2 * W_)   // 2056
#define BS_ (B_ * S_)       // 32768

// ---------------------------------------------------------------------------
// Scratch (__device__ globals; allocation-free rule)
// ---------------------------------------------------------------------------
__device__ __align__(256) __half g_pad_h[B_ * SP_ * H_];   // fp16 padded input
__device__ __align__(256) __half g_xh[2 * BS_ * H_];       // fp16 residual stream per side
__device__ __align__(256) __half g_h[2 * BS_ * H_];        // fp16 hidden per side
__device__ __align__(256) float  g_stats[4 * BS_ * 2];     // (sum, sumsq) x 4 phases
__device__ __align__(256) float  g_q[4 * H_];              // gamma @ W1 per (layer,side)
__device__ __align__(256) float  g_p[4 * H_];              // beta @ W1 + b1
// fp16 weights (W1 blocks pre-scaled by gamma rows), linear layout:
#define OFF_WL  0
#define OFF_WR  1048576
#define OFF_LW1 2097152
#define OFF_LW2 2621440
#define OFF_RW1 3145728
#define OFF_RW2 3670016
__device__ __align__(256) __half g_wh[4194304];

// ---------------------------------------------------------------------------
// PTX helpers
// ---------------------------------------------------------------------------
__device__ __forceinline__ uint32_t smem_u32(const void* p) {
    uint32_t a;
    asm("{ .reg .u64 t; cvta.to.shared.u64 t, %1; cvt.u32.u64 %0, t; }" : "=r"(a) : "l"(p));
    return a;
}
__device__ __forceinline__ void cp_async16(uint32_t dst, const void* src) {
    asm volatile("cp.async.cg.shared.global [%0], [%1], 16;" :: "r"(dst), "l"(src) : "memory");
}
template <int N>
__device__ __forceinline__ void cp_wait() {
    asm volatile("cp.async.wait_group %0;" :: "n"(N) : "memory");
}
#define CP_COMMIT() asm volatile("cp.async.commit_group;" ::: "memory")

__device__ __forceinline__ void ldm_x4(uint32_t r[4], uint32_t addr) {
    asm volatile("ldmatrix.sync.aligned.m8n8.x4.shared.b16 {%0,%1,%2,%3}, [%4];"
        : "=r"(r[0]), "=r"(r[1]), "=r"(r[2]), "=r"(r[3]) : "r"(addr));
}
__device__ __forceinline__ void ldm_x4_t(uint32_t r[4], uint32_t addr) {
    asm volatile("ldmatrix.sync.aligned.m8n8.x4.trans.shared.b16 {%0,%1,%2,%3}, [%4];"
        : "=r"(r[0]), "=r"(r[1]), "=r"(r[2]), "=r"(r[3]) : "r"(addr));
}
__device__ __forceinline__ void mma_f16(float c[4], const uint32_t a[4],
                                        uint32_t b0, uint32_t b1) {
    asm volatile(
        "mma.sync.aligned.m16n8k16.row.col.f32.f16.f16.f32 "
        "{%0,%1,%2,%3}, {%4,%5,%6,%7}, {%8,%9}, {%0,%1,%2,%3};"
        : "+f"(c[0]), "+f"(c[1]), "+f"(c[2]), "+f"(c[3])
        : "r"(a[0]), "r"(a[1]), "r"(a[2]), "r"(a[3]), "r"(b0), "r"(b1));
}

// ---------------------------------------------------------------------------
// One prep kernel: [pad | f2h(+gamma fold into W1) | q/p GEMV | zero stats]
// ---------------------------------------------------------------------------
constexpr int PAD_BLK = 16448;   // B_*SP_*(H_/4)/256
constexpr int F2H_BLK = 2048;    // 524288 uint4 / 256
constexpr int QP_BLK = 8;        // 4 combos * 512 cols / 256
constexpr int ZERO_BLK = 256;    // 65536 float4 / 256

__global__ void prep_all(const float* __restrict__ inp, const float* __restrict__ lp,
                         const float* __restrict__ rp,
                         const float* __restrict__ Wl, const float* __restrict__ Wr,
                         const float* __restrict__ lw1, const float* __restrict__ lw2,
                         const float* __restrict__ rw1, const float* __restrict__ rw2,
                         const float* __restrict__ lg, const float* __restrict__ rg,
                         const float* __restrict__ lbeta, const float* __restrict__ lb1,
                         const float* __restrict__ rbeta, const float* __restrict__ rb1) {
    int blk = blockIdx.x;
    int tid = threadIdx.x;
    if (blk < PAD_BLK) {
        const int H4 = H_ / 4;
        int idx = blk * 256 + tid;
        int h4 = idx % H4;
        int t = idx / H4;
        int p = t % SP_;
        int b = t / SP_;
        float4 v;
        if (p < W_) v = ((const float4*)lp)[p * H4 + h4];
        else if (p < W_ + S_) v = ((const float4*)inp)[((size_t)b * S_ + (p - W_)) * H4 + h4];
        else v = ((const float4*)rp)[(p - W_ - S_) * H4 + h4];
        __half2 h[2];
        h[0] = __floats2half2_rn(v.x, v.y);
        h[1] = __floats2half2_rn(v.z, v.w);
        ((uint2*)g_pad_h)[idx] = *(uint2*)h;
        return;
    }
    blk -= PAD_BLK;
    if (blk < F2H_BLK) {
        int i = blk * 256 + tid;   // uint4 index (8 halves)
        const float* src;
        int off;
        float scale = 1.0f;
        if (i < 131072)      { src = Wl;  off = i; }
        else if (i < 262144) { src = Wr;  off = i - 131072; }
        else if (i < 327680) {
            src = lw1; off = i - 262144;
            scale = lg[(off >> 15) * H_ + (((off & 32767) * 8) >> 9)];
        }
        else if (i < 393216) { src = lw2; off = i - 327680; }
        else if (i < 458752) {
            src = rw1; off = i - 393216;
            scale = rg[(off >> 15) * H_ + (((off & 32767) * 8) >> 9)];
        }
        else                 { src = rw2; off = i - 458752; }
        float4 v0 = ((const float4*)src)[2 * off];
        float4 v1 = ((const float4*)src)[2 * off + 1];
        __half2 h[4];
        h[0] = __floats2half2_rn(v0.x * scale, v0.y * scale);
        h[1] = __floats2half2_rn(v0.z * scale, v0.w * scale);
        h[2] = __floats2half2_rn(v1.x * scale, v1.y * scale);
        h[3] = __floats2half2_rn(v1.z * scale, v1.w * scale);
        ((uint4*)g_wh)[i] = *(uint4*)h;
        return;
    }
    blk -= F2H_BLK;
    if (blk < QP_BLK) {
        int jj = blk * 256 + tid;
        int combo = jj >> 9;
        int j = jj & 511;
        int layer = combo >> 1, side = combo & 1;
        const float* Wm = (side ? rw1 : lw1) + (size_t)layer * H_ * H_;
        const float* ga = (side ? rg : lg) + layer * H_;
        const float* be = (side ? rbeta : lbeta) + layer * H_;
        const float* b1 = (side ? rb1 : lb1) + layer * H_;
        float q = 0.f, p = 0.f;
        for (int k = 0; k < H_; k++) {
            float w = Wm[(size_t)k * H_ + j];
            q += ga[k] * w;
            p += be[k] * w;
        }
        g_q[combo * H_ + j] = q;
        g_p[combo * H_ + j] = p + b1[j];
        return;
    }
    blk -= QP_BLK;
    ((float4*)g_stats)[blk * 256 + tid] = make_float4(0.f, 0.f, 0.f, 0.f);
}

// ---------------------------------------------------------------------------
// fp16 mma.sync GEMM: 128x128 CTA tile, BK=32, 4-stage cp.async, single
// __syncthreads per chunk. After the K-loop, accumulators are staged through
// a 128x132 fp32 smem tile so ALL epilogue global accesses are row-major and
// fully coalesced (the direct fragment-layout stores hit 8 cache lines per
// STG -> 8x LSU replay; that was the dominant cost of the whole network).
//   MODE 0: NT=128, 4 warps 2x2, warp tile 64x64 (long-K)
//   MODE 1/2: NT=256, 8 warps 2x4, warp tile 64x32 (short-K)
// ---------------------------------------------------------------------------
constexpr int A_STAGE_B = 128 * 80;
constexpr int B_STAGE_B = 32 * 272;
constexpr int STAGE_B = A_STAGE_B + B_STAGE_B;  // 18944 B
constexpr int STAGES = 4;
constexpr int SMEM_BYTES = STAGES * STAGE_B;    // 75776 B (>= 128*132*4 = 67584)

template <int MODE, int KT, int NT>
__global__ void __launch_bounds__(NT, 2)
tc_gemm(int woffL, int woffR,
        const float* __restrict__ bL, const float* __restrict__ bR,
        int qp_base, int statsPhase, int ln_phase,
        float* __restrict__ outA, float* __restrict__ outL) {
    constexpr int WNC = NT / 64;          // warps in N: 2 or 4
    constexpr int TNW = 128 / WNC;        // warp tile N: 64 or 32
    constexpr int NP = TNW / 16;
    constexpr int NR = 2 * NP;
    constexpr int LS = 512 / NT;
    constexpr int WARPS = NT / 32;

    extern __shared__ char smraw[];
    const uint32_t sbase = smem_u32(smraw);
    const int tid = threadIdx.x;
    const int lane = tid & 31, wid = tid >> 5;
    const int warpM = wid / WNC, warpN = wid % WNC;
    const int gid = lane >> 2, t4 = lane & 3;
    const int lane15 = lane & 15, laneHi = lane >> 4;
    const int n0 = blockIdx.x * 128;

    int side;
    size_t m0;
    const __half* A;
    if (MODE == 0) {
        side = blockIdx.z >> 4;
        int bb = blockIdx.z & 15;
        m0 = (size_t)bb * S_ + blockIdx.y * 128;
        A = g_pad_h + ((size_t)bb * SP_ + blockIdx.y * 128 + side * (W_ + 1)) * H_;
    } else {
        side = blockIdx.z;
        m0 = (size_t)blockIdx.y * 128;
        A = (MODE == 1 ? g_xh : g_h) + ((size_t)side * BS_ + m0) * H_;
    }
    const __half* Wm = g_wh + (side ? woffR : woffL);
    const float* bias = side ? bR : bL;

    float c[4][NR][4];
#pragma unroll
    for (int i = 0; i < 4; i++)
#pragma unroll
        for (int j = 0; j < NR; j++)
#pragma unroll
            for (int q = 0; q < 4; q++) c[i][j][q] = 0.f;

    auto loadStage = [&](int kt, int s) {
        const int k0 = kt * 32;
        uint32_t base = sbase + (uint32_t)s * STAGE_B;
#pragma unroll
        for (int i = 0; i < LS; i++) {
            int ch = tid + i * NT;
            int ar = ch >> 2, ac = ch & 3;
            cp_async16(base + ar * 80 + ac * 16, A + (size_t)ar * H_ + k0 + ac * 8);
            int br = ch >> 4, bc = ch & 15;
            cp_async16(base + A_STAGE_B + br * 272 + bc * 16,
                       Wm + (size_t)(k0 + br) * H_ + n0 + bc * 8);
        }
        CP_COMMIT();
    };

    loadStage(0, 0);
    if (KT > 1) loadStage(1, 1);
    if (KT > 2) loadStage(2, 2);

    for (int kt = 0; kt < KT; kt++) {
        int rem = KT - 1 - kt;
        if (rem >= 2) cp_wait<2>();
        else if (rem == 1) cp_wait<1>();
        else cp_wait<0>();
        __syncthreads();
        if (kt + 3 < KT) loadStage(kt + 3, (kt + 3) % STAGES);

        const uint32_t a_base = sbase + (uint32_t)((kt % STAGES) * STAGE_B);
        const uint32_t b_base = a_base + A_STAGE_B;
#pragma unroll
        for (int ks = 0; ks < 2; ks++) {
            uint32_t a[4][4], bb2[NP][4];
#pragma unroll
            for (int mr = 0; mr < 4; mr++)
                ldm_x4(a[mr], a_base + (warpM * 64 + mr * 16 + lane15) * 80
                                 + ks * 32 + laneHi * 16);
#pragma unroll
            for (int np = 0; np < NP; np++)
                ldm_x4_t(bb2[np], b_base + (ks * 16 + lane15) * 272
                                    + (warpN * TNW + np * 16 + laneHi * 8) * 2);
#pragma unroll
            for (int mr = 0; mr < 4; mr++)
#pragma unroll
                for (int np = 0; np < NP; np++) {
                    mma_f16(c[mr][2 * np + 0], a[mr], bb2[np][0], bb2[np][1]);
                    mma_f16(c[mr][2 * np + 1], a[mr], bb2[np][2], bb2[np][3]);
                }
        }
    }

    // ---------------- epilogue: stage accumulators through smem ----------------
    __syncthreads();   // all warps done reading stage buffers
    float* sm = (float*)smraw;
#pragma unroll
    for (int mr = 0; mr < 4; mr++)
#pragma unroll
        for (int hh = 0; hh < 2; hh++) {
            int row = warpM * 64 + mr * 16 + gid + hh * 8;
#pragma unroll
            for (int nr = 0; nr < NR; nr++) {
                int col = warpN * TNW + nr * 8 + t4 * 2;
                *(float2*)&sm[row * 132 + col] =
                    make_float2(c[mr][nr][hh * 2 + 0], c[mr][nr][hh * 2 + 1]);
            }
        }
    __syncthreads();

    // row-major coalesced phase: one warp per row, lane covers cols 4l..4l+3
    const int c0 = lane * 4;
    __half* xhSide = g_xh + (size_t)side * BS_ * H_;

    if (MODE == 1) {
        const int cb = (qp_base + side) * H_;
        const float* stats = g_stats + (size_t)(ln_phase + side) * BS_ * 2;
        __half* hSide = g_h + (size_t)side * BS_ * H_;
        const float4 q4 = *(const float4*)(g_q + cb + n0 + c0);
        const float4 p4 = *(const float4*)(g_p + cb + n0 + c0);
        for (int rr = wid; rr < 128; rr += WARPS) {
            size_t r = m0 + rr;
            float4 a4 = *(float4*)&sm[rr * 132 + c0];
            float2 st = *(const float2*)(stats + r * 2);
            float mu = st.x * (1.0f / H_);
            float var = st.y * (1.0f / H_) - mu * mu;
            float rstd = rsqrtf(fmaxf(var, 0.f) + 1e-5f);
            float mt = -rstd * mu;
            float v0 = fmaxf(fmaf(rstd, a4.x, fmaf(mt, q4.x, p4.x)), 0.f);
            float v1 = fmaxf(fmaf(rstd, a4.y, fmaf(mt, q4.y, p4.y)), 0.f);
            float v2 = fmaxf(fmaf(rstd, a4.z, fmaf(mt, q4.z, p4.z)), 0.f);
            float v3 = fmaxf(fmaf(rstd, a4.w, fmaf(mt, q4.w, p4.w)), 0.f);
            __half2 h[2] = {__floats2half2_rn(v0, v1), __floats2half2_rn(v2, v3)};
            *(uint2*)(hSide + r * H_ + n0 + c0) = *(uint2*)h;
        }
        return;
    }

    // MODE 0 / MODE 2
    const float4 b4 = *(const float4*)(bias + n0 + c0);
    float* statsDst = (statsPhase >= 0)
        ? g_stats + (size_t)(statsPhase + side) * BS_ * 2 : (float*)0;

    for (int rr = wid; rr < 128; rr += WARPS) {
        size_t r = m0 + rr;
        float4 a4 = *(float4*)&sm[rr * 132 + c0];
        float v0 = a4.x + b4.x, v1 = a4.y + b4.y, v2 = a4.z + b4.z, v3 = a4.w + b4.w;
        if (MODE == 0) {
            v0 = fmaxf(v0, 0.f); v1 = fmaxf(v1, 0.f);
            v2 = fmaxf(v2, 0.f); v3 = fmaxf(v3, 0.f);
            __half2 h[2] = {__floats2half2_rn(v0, v1), __floats2half2_rn(v2, v3)};
            *(uint2*)(xhSide + r * H_ + n0 + c0) = *(uint2*)h;
        } else {
            uint2 rh = *(const uint2*)(xhSide + r * H_ + n0 + c0);
            float2 r01 = __half22float2(*(__half2*)&rh.x);
            float2 r23 = __half22float2(*(__half2*)&rh.y);
            v0 += r01.x; v1 += r01.y; v2 += r23.x; v3 += r23.y;
            size_t bi = r >> 11, si = r & 2047;
            int ocol = side * H_ + n0 + c0;
            *(float4*)(outA + (si * B_ + bi) * (size_t)(2 * H_) + ocol) =
                make_float4(v0, v1, v2, v3);
            if (outL)
                *(float4*)(outL + (bi * S_ + si) * (size_t)(2 * H_) + ocol) =
                    make_float4(v0, v1, v2, v3);
            if (statsPhase >= 0) {
                __half2 h[2] = {__floats2half2_rn(v0, v1), __floats2half2_rn(v2, v3)};
                *(uint2*)(xhSide + r * H_ + n0 + c0) = *(uint2*)h;
            }
        }
        if (MODE == 0 || statsPhase >= 0) {
            float s = v0 + v1 + v2 + v3;
            float sq = v0 * v0 + v1 * v1 + v2 * v2 + v3 * v3;
#pragma unroll
            for (int o = 16; o; o >>= 1) {
                s += __shfl_xor_sync(0xffffffffu, s, o);
                sq += __shfl_xor_sync(0xffffffffu, sq, o);
            }
            if (lane == 0) {
                atomicAdd(statsDst + r * 2, s);
                atomicAdd(statsDst + r * 2 + 1, sq);
            }
        }
    }
}

// ---------------------------------------------------------------------------
extern "C" void kernel_launch(void* const* d_in, const int* in_sizes, int n_in,
                              void* d_out, int out_size) {
    const float* inputs = (const float*)d_in[0];
    const float* lp     = (const float*)d_in[1];
    const float* rp     = (const float*)d_in[2];
    const float* Wl     = (const float*)d_in[3];
    const float* bl     = (const float*)d_in[4];
    const float* Wr     = (const float*)d_in[5];
    const float* br     = (const float*)d_in[6];
    const float* lw1    = (const float*)d_in[7];
    const float* lb1    = (const float*)d_in[8];
    const float* lw2    = (const float*)d_in[9];
    const float* lb2    = (const float*)d_in[10];
    const float* lg     = (const float*)d_in[11];
    const float* lbeta  = (const float*)d_in[12];
    const float* rw1    = (const float*)d_in[13];
    const float* rb1    = (const float*)d_in[14];
    const float* rw2    = (const float*)d_in[15];
    const float* rb2    = (const float*)d_in[16];
    const float* rg     = (const float*)d_in[17];
    const float* rbeta  = (const float*)d_in[18];
    float* out = (float*)d_out;
    (void)in_sizes; (void)n_in; (void)out_size;

    cudaFuncSetAttribute(tc_gemm<0, 64, 128>,
                         cudaFuncAttributeMaxDynamicSharedMemorySize, SMEM_BYTES);
    cudaFuncSetAttribute(tc_gemm<1, 16, 256>,
                         cudaFuncAttributeMaxDynamicSharedMemorySize, SMEM_BYTES);
    cudaFuncSetAttribute(tc_gemm<2, 16, 256>,
                         cudaFuncAttributeMaxDynamicSharedMemorySize, SMEM_BYTES);

    // 1) merged prep: pad + f2h(+gamma fold) + q/p + stats zero
    prep_all<<<PAD_BLK + F2H_BLK + QP_BLK + ZERO_BLK, 256>>>(
        inputs, lp, rp, Wl, Wr, lw1, lw2, rw1, rw2,
        lg, rg, lbeta, lb1, rbeta, rb1);

    // 2) wide projections, L+R merged (128 threads, 64x64 warp tiles)
    tc_gemm<0, 64, 128><<<dim3(4, 16, 32), 128, SMEM_BYTES>>>(
        OFF_WL, OFF_WR, bl, br, 0, 0, 0, nullptr, nullptr);

    // 3) residual FF layers, L+R merged (256 threads, 64x32 warp tiles)
    for (int i = 0; i < L_; i++) {
        bool last = (i == L_ - 1);
        tc_gemm<1, 16, 256><<<dim3(4, 256, 2), 256, SMEM_BYTES>>>(
            OFF_LW1 + i * 262144, OFF_RW1 + i * 262144,
            nullptr, nullptr,
            i * 2, -1, (i == 0) ? 0 : 2, nullptr, nullptr);

        float* oall = out + (size_t)i * S_ * B_ * 2 * H_;
        float* olast = last ? out + (size_t)L_ * S_ * B_ * 2 * H_ : nullptr;
        tc_gemm<2, 16, 256><<<dim3(4, 256, 2), 256, SMEM_BYTES>>>(
            OFF_LW2 + i * 262144, OFF_RW2 + i * 262144,
            lb2 + (size_t)i * H_, rb2 + (size_t)i * H_,
            0, last ? -1 : 2, 0, oall, olast);
    }
}

// round 14
// speedup vs baseline: 1.4462x; 1.4462x over previous
#include <cuda_runtime.h>
#include <cuda_fp16.h>
#include <cstdint>

#define B_ 16
#define S_ 2048
#define H_ 512
#define W_ 4
#define L_ 2
#define SP_ (S_ + 2 * W_)   // 2056
#define BS_ (B_ * S_)       // 32768

// ---------------------------------------------------------------------------
// Scratch (__device__ globals; allocation-free rule)
// ---------------------------------------------------------------------------
__device__ __align__(256) __half g_pad_h[B_ * SP_ * H_];     // fp16 padded input
__device__ __align__(256) float  g_lo[BS_ * H_];             // fp32 residual L
__device__ __align__(256) float  g_ro[BS_ * H_];             // fp32 residual R
__device__ __align__(256) __half g_u[2 * BS_ * H_];          // fp16 x*gamma per side
__device__ __align__(256) __half g_h[2 * BS_ * H_];          // fp16 hidden per side
__device__ __align__(256) float  g_stats[4 * BS_ * 2];       // (sum, sumsq) x 4 phases
__device__ __align__(256) float  g_q[4 * H_];                // gamma @ W1 per (layer,side)
__device__ __align__(256) float  g_p[4 * H_];                // beta @ W1 + b1
#define OFF_WL  0
#define OFF_WR  1048576
#define OFF_LW1 2097152
#define OFF_LW2 2621440
#define OFF_RW1 3145728
#define OFF_RW2 3670016
__device__ __align__(256) __half g_wh[4194304];

// ---------------------------------------------------------------------------
// PTX helpers
// ---------------------------------------------------------------------------
__device__ __forceinline__ uint32_t smem_u32(const void* p) {
    uint32_t a;
    asm("{ .reg .u64 t; cvta.to.shared.u64 t, %1; cvt.u32.u64 %0, t; }" : "=r"(a) : "l"(p));
    return a;
}
__device__ __forceinline__ void cp_async16(uint32_t dst, const void* src) {
    asm volatile("cp.async.cg.shared.global [%0], [%1], 16;" :: "r"(dst), "l"(src) : "memory");
}
template <int N>
__device__ __forceinline__ void cp_wait() {
    asm volatile("cp.async.wait_group %0;" :: "n"(N) : "memory");
}
#define CP_COMMIT() asm volatile("cp.async.commit_group;" ::: "memory")

__device__ __forceinline__ void ldm_x4(uint32_t r[4], uint32_t addr) {
    asm volatile("ldmatrix.sync.aligned.m8n8.x4.shared.b16 {%0,%1,%2,%3}, [%4];"
        : "=r"(r[0]), "=r"(r[1]), "=r"(r[2]), "=r"(r[3]) : "r"(addr));
}
__device__ __forceinline__ void ldm_x4_t(uint32_t r[4], uint32_t addr) {
    asm volatile("ldmatrix.sync.aligned.m8n8.x4.trans.shared.b16 {%0,%1,%2,%3}, [%4];"
        : "=r"(r[0]), "=r"(r[1]), "=r"(r[2]), "=r"(r[3]) : "r"(addr));
}
__device__ __forceinline__ void mma_f16(float c[4], const uint32_t a[4],
                                        uint32_t b0, uint32_t b1) {
    asm volatile(
        "mma.sync.aligned.m16n8k16.row.col.f32.f16.f16.f32 "
        "{%0,%1,%2,%3}, {%4,%5,%6,%7}, {%8,%9}, {%0,%1,%2,%3};"
        : "+f"(c[0]), "+f"(c[1]), "+f"(c[2]), "+f"(c[3])
        : "r"(a[0]), "r"(a[1]), "r"(a[2]), "r"(a[3]), "r"(b0), "r"(b1));
}

// ---------------------------------------------------------------------------
// convert ALL fp32 weights -> fp16 into g_wh (linear layout)
// ---------------------------------------------------------------------------
__global__ void f2h_all(const float* __restrict__ Wl, const float* __restrict__ Wr,
                        const float* __restrict__ lw1, const float* __restrict__ lw2,
                        const float* __restrict__ rw1, const float* __restrict__ rw2) {
    int i = blockIdx.x * blockDim.x + threadIdx.x;
    if (i >= 524288) return;
    const float* src;
    int off;
    if (i < 131072)      { src = Wl;  off = i; }
    else if (i < 262144) { src = Wr;  off = i - 131072; }
    else if (i < 327680) { src = lw1; off = i - 262144; }
    else if (i < 393216) { src = lw2; off = i - 327680; }
    else if (i < 458752) { src = rw1; off = i - 393216; }
    else                 { src = rw2; off = i - 458752; }
    float4 v0 = ((const float4*)src)[2 * off];
    float4 v1 = ((const float4*)src)[2 * off + 1];
    __half2 h[4];
    h[0] = __floats2half2_rn(v0.x, v0.y);
    h[1] = __floats2half2_rn(v0.z, v0.w);
    h[2] = __floats2half2_rn(v1.x, v1.y);
    h[3] = __floats2half2_rn(v1.z, v1.w);
    ((uint4*)g_wh)[i] = *(uint4*)h;
}

// ---------------------------------------------------------------------------
// prep: q = gamma @ W1, p = beta @ W1 + b1, per combo = layer*2 + side
// ---------------------------------------------------------------------------
__global__ void prep_qp(const float* __restrict__ lw1, const float* __restrict__ rw1,
                        const float* __restrict__ lg, const float* __restrict__ lbeta,
                        const float* __restrict__ lb1,
                        const float* __restrict__ rg, const float* __restrict__ rbeta,
                        const float* __restrict__ rb1) {
    int combo = blockIdx.y;
    int layer = combo >> 1, side = combo & 1;
    const float* Wm = (side ? rw1 : lw1) + (size_t)layer * H_ * H_;
    const float* ga = (side ? rg : lg) + layer * H_;
    const float* be = (side ? rbeta : lbeta) + layer * H_;
    const float* b1 = (side ? rb1 : lb1) + layer * H_;
    int j = blockIdx.x * 128 + threadIdx.x;
    float q = 0.f, p = 0.f;
    for (int k = 0; k < H_; k++) {
        float w = Wm[(size_t)k * H_ + j];
        q += ga[k] * w;
        p += be[k] * w;
    }
    g_q[combo * H_ + j] = q;
    g_p[combo * H_ + j] = p + b1[j];
}

// ---------------------------------------------------------------------------
// pad: [left ; inputs ; right] -> g_pad_h (fp16)
// ---------------------------------------------------------------------------
__global__ void pad_kernel(const float* __restrict__ inp,
                           const float* __restrict__ lp,
                           const float* __restrict__ rp) {
    const int H4 = H_ / 4;
    int idx = blockIdx.x * blockDim.x + threadIdx.x;
    if (idx >= B_ * SP_ * H4) return;
    int h4 = idx % H4;
    int t = idx / H4;
    int p = t % SP_;
    int b = t / SP_;
    float4 v;
    if (p < W_) v = ((const float4*)lp)[p * H4 + h4];
    else if (p < W_ + S_) v = ((const float4*)inp)[((size_t)b * S_ + (p - W_)) * H4 + h4];
    else v = ((const float4*)rp)[(p - W_ - S_) * H4 + h4];
    __half2 h[2];
    h[0] = __floats2half2_rn(v.x, v.y);
    h[1] = __floats2half2_rn(v.z, v.w);
    ((uint2*)g_pad_h)[idx] = *(uint2*)h;
}

// ---------------------------------------------------------------------------
// fp16 mma.sync GEMM: 128x128 CTA tile, BK=32, 4-stage cp.async, single
// __syncthreads per chunk.
//   MODE 0: NT=128, 2x2 warps, 64x64 tiles; original fragment epilogue
//           (254 regs — MUST stay untouched, staging there causes spills).
//   MODE 1/2: NT=256, 2x4 warps, 64x32 tiles; smem-staged row-major epilogue
//           (fragment-layout global stores hit 8 lines per STG -> 8x replay).
// ---------------------------------------------------------------------------
constexpr int A_STAGE_B = 128 * 80;
constexpr int B_STAGE_B = 32 * 272;
constexpr int STAGE_B = A_STAGE_B + B_STAGE_B;  // 18944 B
constexpr int STAGES = 4;
constexpr int SMEM_BYTES = STAGES * STAGE_B;    // 75776 B (>= 128*132*4)

template <int MODE, int KT, int NT>
__global__ void __launch_bounds__(NT, 2)
tc_gemm(int woffL, int woffR,
        const float* __restrict__ bL, const float* __restrict__ bR,
        const float* __restrict__ gamL, const float* __restrict__ gamR,
        int qp_base, int statsPhase, int ln_phase,
        float* __restrict__ outA, float* __restrict__ outL) {
    constexpr int WNC = NT / 64;
    constexpr int TNW = 128 / WNC;
    constexpr int NP = TNW / 16;
    constexpr int NR = 2 * NP;
    constexpr int LS = 512 / NT;
    constexpr int WARPS = NT / 32;

    extern __shared__ char smraw[];
    const uint32_t sbase = smem_u32(smraw);
    const int tid = threadIdx.x;
    const int lane = tid & 31, wid = tid >> 5;
    const int warpM = wid / WNC, warpN = wid % WNC;
    const int gid = lane >> 2, t4 = lane & 3;
    const int lane15 = lane & 15, laneHi = lane >> 4;
    const int n0 = blockIdx.x * 128;

    int side;
    size_t m0;
    const __half* A;
    if (MODE == 0) {
        side = blockIdx.z >> 4;
        int bb = blockIdx.z & 15;
        m0 = (size_t)bb * S_ + blockIdx.y * 128;
        A = g_pad_h + ((size_t)bb * SP_ + blockIdx.y * 128 + side * (W_ + 1)) * H_;
    } else {
        side = blockIdx.z;
        m0 = (size_t)blockIdx.y * 128;
        A = (MODE == 1 ? g_u : g_h) + ((size_t)side * BS_ + m0) * H_;
    }
    const __half* Wm = g_wh + (side ? woffR : woffL);
    float* X = side ? g_ro : g_lo;
    const float* bias = side ? bR : bL;
    const float* gam = side ? gamR : gamL;

    float c[4][NR][4];
#pragma unroll
    for (int i = 0; i < 4; i++)
#pragma unroll
        for (int j = 0; j < NR; j++)
#pragma unroll
            for (int q = 0; q < 4; q++) c[i][j][q] = 0.f;

    auto loadStage = [&](int kt, int s) {
        const int k0 = kt * 32;
        uint32_t base = sbase + (uint32_t)s * STAGE_B;
#pragma unroll
        for (int i = 0; i < LS; i++) {
            int ch = tid + i * NT;
            int ar = ch >> 2, ac = ch & 3;
            cp_async16(base + ar * 80 + ac * 16, A + (size_t)ar * H_ + k0 + ac * 8);
            int br = ch >> 4, bc = ch & 15;
            cp_async16(base + A_STAGE_B + br * 272 + bc * 16,
                       Wm + (size_t)(k0 + br) * H_ + n0 + bc * 8);
        }
        CP_COMMIT();
    };

    loadStage(0, 0);
    if (KT > 1) loadStage(1, 1);
    if (KT > 2) loadStage(2, 2);

    for (int kt = 0; kt < KT; kt++) {
        int rem = KT - 1 - kt;
        if (rem >= 2) cp_wait<2>();
        else if (rem == 1) cp_wait<1>();
        else cp_wait<0>();
        __syncthreads();
        if (kt + 3 < KT) loadStage(kt + 3, (kt + 3) % STAGES);

        const uint32_t a_base = sbase + (uint32_t)((kt % STAGES) * STAGE_B);
        const uint32_t b_base = a_base + A_STAGE_B;
#pragma unroll
        for (int ks = 0; ks < 2; ks++) {
            uint32_t a[4][4], bb2[NP][4];
#pragma unroll
            for (int mr = 0; mr < 4; mr++)
                ldm_x4(a[mr], a_base + (warpM * 64 + mr * 16 + lane15) * 80
                                 + ks * 32 + laneHi * 16);
#pragma unroll
            for (int np = 0; np < NP; np++)
                ldm_x4_t(bb2[np], b_base + (ks * 16 + lane15) * 272
                                    + (warpN * TNW + np * 16 + laneHi * 8) * 2);
#pragma unroll
            for (int mr = 0; mr < 4; mr++)
#pragma unroll
                for (int np = 0; np < NP; np++) {
                    mma_f16(c[mr][2 * np + 0], a[mr], bb2[np][0], bb2[np][1]);
                    mma_f16(c[mr][2 * np + 1], a[mr], bb2[np][2], bb2[np][3]);
                }
        }
    }

    __half* uSide = g_u + (size_t)side * BS_ * H_;

    // ============== MODE 0: original fragment epilogue (unchanged) ==============
    if (MODE == 0) {
        const int colbase = n0 + warpN * TNW + t4 * 2;
        float* statsDst = g_stats + (size_t)side * BS_ * 2;
#pragma unroll
        for (int mr = 0; mr < 4; mr++) {
#pragma unroll
            for (int hh = 0; hh < 2; hh++) {
                size_t r = m0 + warpM * 64 + mr * 16 + gid + hh * 8;
                float* xrow = X + r * H_;
                float s = 0.f, sq = 0.f;
#pragma unroll
                for (int nr = 0; nr < NR; nr++) {
                    int col = colbase + nr * 8;
                    float2 bv = *(const float2*)(bias + col);
                    float v0 = fmaxf(c[mr][nr][hh * 2 + 0] + bv.x, 0.f);
                    float v1 = fmaxf(c[mr][nr][hh * 2 + 1] + bv.y, 0.f);
                    *(float2*)(xrow + col) = make_float2(v0, v1);
                    float2 gv = *(const float2*)(gam + col);
                    *(__half2*)(uSide + r * H_ + col) =
                        __floats2half2_rn(v0 * gv.x, v1 * gv.y);
                    s += v0 + v1;
                    sq += v0 * v0 + v1 * v1;
                }
                s += __shfl_xor_sync(0xffffffffu, s, 1);
                sq += __shfl_xor_sync(0xffffffffu, sq, 1);
                s += __shfl_xor_sync(0xffffffffu, s, 2);
                sq += __shfl_xor_sync(0xffffffffu, sq, 2);
                if (t4 == 0) {
                    atomicAdd(statsDst + r * 2, s);
                    atomicAdd(statsDst + r * 2 + 1, sq);
                }
            }
        }
        return;
    }

    // ============== MODE 1/2: smem-staged, fully coalesced epilogue ============
    __syncthreads();   // all warps done reading stage buffers
    float* sm = (float*)smraw;
#pragma unroll
    for (int mr = 0; mr < 4; mr++)
#pragma unroll
        for (int hh = 0; hh < 2; hh++) {
            int row = warpM * 64 + mr * 16 + gid + hh * 8;
#pragma unroll
            for (int nr = 0; nr < NR; nr++) {
                int col = warpN * TNW + nr * 8 + t4 * 2;
                *(float2*)&sm[row * 132 + col] =
                    make_float2(c[mr][nr][hh * 2 + 0], c[mr][nr][hh * 2 + 1]);
            }
        }
    __syncthreads();

    const int c0 = lane * 4;   // one warp per row; lane covers cols 4l..4l+3

    if (MODE == 1) {
        const int cb = (qp_base + side) * H_;
        const float* stats = g_stats + (size_t)(ln_phase + side) * BS_ * 2;
        __half* hSide = g_h + (size_t)side * BS_ * H_;
        const float4 q4 = *(const float4*)(g_q + cb + n0 + c0);
        const float4 p4 = *(const float4*)(g_p + cb + n0 + c0);
        for (int rr = wid; rr < 128; rr += WARPS) {
            size_t r = m0 + rr;
            float4 a4 = *(float4*)&sm[rr * 132 + c0];
            float2 st = *(const float2*)(stats + r * 2);
            float mu = st.x * (1.0f / H_);
            float var = st.y * (1.0f / H_) - mu * mu;
            float rstd = rsqrtf(fmaxf(var, 0.f) + 1e-5f);
            float mt = -rstd * mu;
            float v0 = fmaxf(fmaf(rstd, a4.x, fmaf(mt, q4.x, p4.x)), 0.f);
            float v1 = fmaxf(fmaf(rstd, a4.y, fmaf(mt, q4.y, p4.y)), 0.f);
            float v2 = fmaxf(fmaf(rstd, a4.z, fmaf(mt, q4.z, p4.z)), 0.f);
            float v3 = fmaxf(fmaf(rstd, a4.w, fmaf(mt, q4.w, p4.w)), 0.f);
            __half2 h[2] = {__floats2half2_rn(v0, v1), __floats2half2_rn(v2, v3)};
            *(uint2*)(hSide + r * H_ + n0 + c0) = *(uint2*)h;
        }
        return;
    }

    // MODE 2
    const float4 b4 = *(const float4*)(bias + n0 + c0);
    float4 g4v = make_float4(0.f, 0.f, 0.f, 0.f);
    if (statsPhase >= 0) g4v = *(const float4*)(gam + n0 + c0);
    float* statsDst = (statsPhase >= 0)
        ? g_stats + (size_t)(statsPhase + side) * BS_ * 2 : (float*)0;

    for (int rr = wid; rr < 128; rr += WARPS) {
        size_t r = m0 + rr;
        float4 a4 = *(float4*)&sm[rr * 132 + c0];
        float4 res = *(const float4*)(X + r * H_ + n0 + c0);
        float v0 = a4.x + b4.x + res.x;
        float v1 = a4.y + b4.y + res.y;
        float v2 = a4.z + b4.z + res.z;
        float v3 = a4.w + b4.w + res.w;
        size_t bi = r >> 11, si = r & 2047;
        int ocol = side * H_ + n0 + c0;
        *(float4*)(outA + (si * B_ + bi) * (size_t)(2 * H_) + ocol) =
            make_float4(v0, v1, v2, v3);
        if (outL)
            *(float4*)(outL + (bi * S_ + si) * (size_t)(2 * H_) + ocol) =
                make_float4(v0, v1, v2, v3);
        if (statsDst) {
            *(float4*)(X + r * H_ + n0 + c0) = make_float4(v0, v1, v2, v3);
            __half2 h[2] = {__floats2half2_rn(v0 * g4v.x, v1 * g4v.y),
                            __floats2half2_rn(v2 * g4v.z, v3 * g4v.w)};
            *(uint2*)(uSide + r * H_ + n0 + c0) = *(uint2*)h;
            float s = v0 + v1 + v2 + v3;
            float sq = v0 * v0 + v1 * v1 + v2 * v2 + v3 * v3;
#pragma unroll
            for (int o = 16; o; o >>= 1) {
                s += __shfl_xor_sync(0xffffffffu, s, o);
                sq += __shfl_xor_sync(0xffffffffu, sq, o);
            }
            if (lane == 0) {
                atomicAdd(statsDst + r * 2, s);
                atomicAdd(statsDst + r * 2 + 1, sq);
            }
        }
    }
}

// ---------------------------------------------------------------------------
extern "C" void kernel_launch(void* const* d_in, const int* in_sizes, int n_in,
                              void* d_out, int out_size) {
    const float* inputs = (const float*)d_in[0];
    const float* lp     = (const float*)d_in[1];
    const float* rp     = (const float*)d_in[2];
    const float* Wl     = (const float*)d_in[3];
    const float* bl     = (const float*)d_in[4];
    const float* Wr     = (const float*)d_in[5];
    const float* br     = (const float*)d_in[6];
    const float* lw1    = (const float*)d_in[7];
    const float* lb1    = (const float*)d_in[8];
    const float* lw2    = (const float*)d_in[9];
    const float* lb2    = (const float*)d_in[10];
    const float* lg     = (const float*)d_in[11];
    const float* lbeta  = (const float*)d_in[12];
    const float* rw1    = (const float*)d_in[13];
    const float* rb1    = (const float*)d_in[14];
    const float* rw2    = (const float*)d_in[15];
    const float* rb2    = (const float*)d_in[16];
    const float* rg     = (const float*)d_in[17];
    const float* rbeta  = (const float*)d_in[18];
    float* out = (float*)d_out;
    (void)in_sizes; (void)n_in; (void)out_size;

    cudaFuncSetAttribute(tc_gemm<0, 64, 128>,
                         cudaFuncAttributeMaxDynamicSharedMemorySize, SMEM_BYTES);
    cudaFuncSetAttribute(tc_gemm<1, 16, 256>,
                         cudaFuncAttributeMaxDynamicSharedMemorySize, SMEM_BYTES);
    cudaFuncSetAttribute(tc_gemm<2, 16, 256>,
                         cudaFuncAttributeMaxDynamicSharedMemorySize, SMEM_BYTES);

    // 0) zero stats
    float* statsPtr;
    cudaGetSymbolAddress((void**)&statsPtr, g_stats);
    cudaMemsetAsync(statsPtr, 0, 4 * BS_ * 2 * sizeof(float));

    // 1) pad + weight convert + LN-fold precompute
    int padTotal = B_ * SP_ * (H_ / 4);
    pad_kernel<<<(padTotal + 255) / 256, 256>>>(inputs, lp, rp);
    f2h_all<<<2048, 256>>>(Wl, Wr, lw1, lw2, rw1, rw2);
    prep_qp<<<dim3(4, 4), 128>>>(lw1, rw1, lg, lbeta, lb1, rg, rbeta, rb1);

    // 2) wide projections, L+R merged (128 threads, 64x64 warp tiles)
    tc_gemm<0, 64, 128><<<dim3(4, 16, 32), 128, SMEM_BYTES>>>(
        OFF_WL, OFF_WR, bl, br, lg, rg, 0, 0, 0, nullptr, nullptr);

    // 3) residual FF layers, L+R merged (256 threads, 64x32 warp tiles)
    for (int i = 0; i < L_; i++) {
        bool last = (i == L_ - 1);
        tc_gemm<1, 16, 256><<<dim3(4, 256, 2), 256, SMEM_BYTES>>>(
            OFF_LW1 + i * 262144, OFF_RW1 + i * 262144,
            nullptr, nullptr, nullptr, nullptr,
            i * 2, -1, (i == 0) ? 0 : 2, nullptr, nullptr);

        float* oall = out + (size_t)i * S_ * B_ * 2 * H_;
        float* olast = last ? out + (size_t)L_ * S_ * B_ * 2 * H_ : nullptr;
        tc_gemm<2, 16, 256><<<dim3(4, 256, 2), 256, SMEM_BYTES>>>(
            OFF_LW2 + i * 262144, OFF_RW2 + i * 262144,
            lb2 + (size_t)i * H_, rb2 + (size_t)i * H_,
            last ? nullptr : lg + (size_t)(i + 1) * H_,
            last ? nullptr : rg + (size_t)(i + 1) * H_,
            0, last ? -1 : 2, 0, oall, olast);
    }
}

// round 15
// speedup vs baseline: 1.4621x; 1.0110x over previous
#include <cuda_runtime.h>
#include <cuda_fp16.h>
#include <cstdint>

#define B_ 16
#define S_ 2048
#define H_ 512
#define W_ 4
#define L_ 2
#define SP_ (S_ + 2 * W_)   // 2056
#define BS_ (B_ * S_)       // 32768

// ---------------------------------------------------------------------------
// Scratch (__device__ globals; allocation-free rule)
// ---------------------------------------------------------------------------
__device__ __align__(256) __half g_pad_h[B_ * SP_ * H_];     // fp16 padded input
__device__ __align__(256) float  g_lo[BS_ * H_];             // fp32 residual L
__device__ __align__(256) float  g_ro[BS_ * H_];             // fp32 residual R
__device__ __align__(256) __half g_u[2 * BS_ * H_];          // fp16 x*gamma per side
__device__ __align__(256) __half g_h[2 * BS_ * H_];          // fp16 hidden per side
__device__ __align__(256) float  g_stats[4 * BS_ * 2];       // (sum, sumsq) x 4 phases
__device__ __align__(256) float  g_q[4 * H_];                // gamma @ W1 per (layer,side)
__device__ __align__(256) float  g_p[4 * H_];                // beta @ W1 + b1
#define OFF_WL  0
#define OFF_WR  1048576
#define OFF_LW1 2097152
#define OFF_LW2 2621440
#define OFF_RW1 3145728
#define OFF_RW2 3670016
__device__ __align__(256) __half g_wh[4194304];

// ---------------------------------------------------------------------------
// PTX helpers
// ---------------------------------------------------------------------------
__device__ __forceinline__ uint32_t smem_u32(const void* p) {
    uint32_t a;
    asm("{ .reg .u64 t; cvta.to.shared.u64 t, %1; cvt.u32.u64 %0, t; }" : "=r"(a) : "l"(p));
    return a;
}
__device__ __forceinline__ void cp_async16(uint32_t dst, const void* src) {
    asm volatile("cp.async.cg.shared.global [%0], [%1], 16;" :: "r"(dst), "l"(src) : "memory");
}
template <int N>
__device__ __forceinline__ void cp_wait() {
    asm volatile("cp.async.wait_group %0;" :: "n"(N) : "memory");
}
#define CP_COMMIT() asm volatile("cp.async.commit_group;" ::: "memory")

__device__ __forceinline__ void ldm_x4(uint32_t r[4], uint32_t addr) {
    asm volatile("ldmatrix.sync.aligned.m8n8.x4.shared.b16 {%0,%1,%2,%3}, [%4];"
        : "=r"(r[0]), "=r"(r[1]), "=r"(r[2]), "=r"(r[3]) : "r"(addr));
}
__device__ __forceinline__ void ldm_x4_t(uint32_t r[4], uint32_t addr) {
    asm volatile("ldmatrix.sync.aligned.m8n8.x4.trans.shared.b16 {%0,%1,%2,%3}, [%4];"
        : "=r"(r[0]), "=r"(r[1]), "=r"(r[2]), "=r"(r[3]) : "r"(addr));
}
__device__ __forceinline__ void mma_f16(float c[4], const uint32_t a[4],
                                        uint32_t b0, uint32_t b1) {
    asm volatile(
        "mma.sync.aligned.m16n8k16.row.col.f32.f16.f16.f32 "
        "{%0,%1,%2,%3}, {%4,%5,%6,%7}, {%8,%9}, {%0,%1,%2,%3};"
        : "+f"(c[0]), "+f"(c[1]), "+f"(c[2]), "+f"(c[3])
        : "r"(a[0]), "r"(a[1]), "r"(a[2]), "r"(a[3]), "r"(b0), "r"(b1));
}

// ---------------------------------------------------------------------------
// One prep kernel: [pad | f2h | q/p GEMV | zero stats], block-range dispatch
// ---------------------------------------------------------------------------
constexpr int PAD_BLK = 16448;   // B_*SP_*(H_/4)/256
constexpr int F2H_BLK = 2048;    // 524288 uint4 / 256
constexpr int QP_BLK = 8;        // 4 combos * 512 cols / 256
constexpr int ZERO_BLK = 256;    // 65536 float4 / 256

__global__ void prep_all(const float* __restrict__ inp, const float* __restrict__ lp,
                         const float* __restrict__ rp,
                         const float* __restrict__ Wl, const float* __restrict__ Wr,
                         const float* __restrict__ lw1, const float* __restrict__ lw2,
                         const float* __restrict__ rw1, const float* __restrict__ rw2,
                         const float* __restrict__ lg, const float* __restrict__ rg,
                         const float* __restrict__ lbeta, const float* __restrict__ lb1,
                         const float* __restrict__ rbeta, const float* __restrict__ rb1) {
    int blk = blockIdx.x;
    int tid = threadIdx.x;
    if (blk < PAD_BLK) {
        // pad: [left ; inputs ; right] -> g_pad_h (fp16)
        const int H4 = H_ / 4;
        int idx = blk * 256 + tid;
        int h4 = idx % H4;
        int t = idx / H4;
        int p = t % SP_;
        int b = t / SP_;
        float4 v;
        if (p < W_) v = ((const float4*)lp)[p * H4 + h4];
        else if (p < W_ + S_) v = ((const float4*)inp)[((size_t)b * S_ + (p - W_)) * H4 + h4];
        else v = ((const float4*)rp)[(p - W_ - S_) * H4 + h4];
        __half2 h[2];
        h[0] = __floats2half2_rn(v.x, v.y);
        h[1] = __floats2half2_rn(v.z, v.w);
        ((uint2*)g_pad_h)[idx] = *(uint2*)h;
        return;
    }
    blk -= PAD_BLK;
    if (blk < F2H_BLK) {
        // fp32 -> fp16 weights (plain convert; gamma NOT folded)
        int i = blk * 256 + tid;   // uint4 index (8 halves)
        const float* src;
        int off;
        if (i < 131072)      { src = Wl;  off = i; }
        else if (i < 262144) { src = Wr;  off = i - 131072; }
        else if (i < 327680) { src = lw1; off = i - 262144; }
        else if (i < 393216) { src = lw2; off = i - 327680; }
        else if (i < 458752) { src = rw1; off = i - 393216; }
        else                 { src = rw2; off = i - 458752; }
        float4 v0 = ((const float4*)src)[2 * off];
        float4 v1 = ((const float4*)src)[2 * off + 1];
        __half2 h[4];
        h[0] = __floats2half2_rn(v0.x, v0.y);
        h[1] = __floats2half2_rn(v0.z, v0.w);
        h[2] = __floats2half2_rn(v1.x, v1.y);
        h[3] = __floats2half2_rn(v1.z, v1.w);
        ((uint4*)g_wh)[i] = *(uint4*)h;
        return;
    }
    blk -= F2H_BLK;
    if (blk < QP_BLK) {
        // q = gamma @ W1, p = beta @ W1 + b1 (fp32 W1)
        int jj = blk * 256 + tid;
        int combo = jj >> 9;
        int j = jj & 511;
        int layer = combo >> 1, side = combo & 1;
        const float* Wm = (side ? rw1 : lw1) + (size_t)layer * H_ * H_;
        const float* ga = (side ? rg : lg) + layer * H_;
        const float* be = (side ? rbeta : lbeta) + layer * H_;
        const float* b1 = (side ? rb1 : lb1) + layer * H_;
        float q = 0.f, p = 0.f;
        for (int k = 0; k < H_; k++) {
            float w = Wm[(size_t)k * H_ + j];
            q += ga[k] * w;
            p += be[k] * w;
        }
        g_q[combo * H_ + j] = q;
        g_p[combo * H_ + j] = p + b1[j];
        return;
    }
    blk -= QP_BLK;
    // zero stats
    ((float4*)g_stats)[blk * 256 + tid] = make_float4(0.f, 0.f, 0.f, 0.f);
}

// ---------------------------------------------------------------------------
// fp16 mma.sync GEMM: 128x128 CTA tile, BK=32, 4-stage cp.async, single
// __syncthreads per chunk.
//   MODE 0: NT=128, 2x2 warps, 64x64 tiles; fragment epilogue (222 regs —
//           stays untouched, staging there spills).
//   MODE 1/2: NT=256, 2x4 warps, 64x32 tiles; smem-staged row-major epilogue.
// ---------------------------------------------------------------------------
constexpr int A_STAGE_B = 128 * 80;
constexpr int B_STAGE_B = 32 * 272;
constexpr int STAGE_B = A_STAGE_B + B_STAGE_B;  // 18944 B
constexpr int STAGES = 4;
constexpr int SMEM_BYTES = STAGES * STAGE_B;    // 75776 B (>= 128*132*4)

template <int MODE, int KT, int NT>
__global__ void __launch_bounds__(NT, 2)
tc_gemm(int woffL, int woffR,
        const float* __restrict__ bL, const float* __restrict__ bR,
        const float* __restrict__ gamL, const float* __restrict__ gamR,
        int qp_base, int statsPhase, int ln_phase,
        float* __restrict__ outA, float* __restrict__ outL) {
    constexpr int WNC = NT / 64;
    constexpr int TNW = 128 / WNC;
    constexpr int NP = TNW / 16;
    constexpr int NR = 2 * NP;
    constexpr int LS = 512 / NT;
    constexpr int WARPS = NT / 32;

    extern __shared__ char smraw[];
    const uint32_t sbase = smem_u32(smraw);
    const int tid = threadIdx.x;
    const int lane = tid & 31, wid = tid >> 5;
    const int warpM = wid / WNC, warpN = wid % WNC;
    const int gid = lane >> 2, t4 = lane & 3;
    const int lane15 = lane & 15, laneHi = lane >> 4;
    const int n0 = blockIdx.x * 128;

    int side;
    size_t m0;
    const __half* A;
    if (MODE == 0) {
        side = blockIdx.z >> 4;
        int bb = blockIdx.z & 15;
        m0 = (size_t)bb * S_ + blockIdx.y * 128;
        A = g_pad_h + ((size_t)bb * SP_ + blockIdx.y * 128 + side * (W_ + 1)) * H_;
    } else {
        side = blockIdx.z;
        m0 = (size_t)blockIdx.y * 128;
        A = (MODE == 1 ? g_u : g_h) + ((size_t)side * BS_ + m0) * H_;
    }
    const __half* Wm = g_wh + (side ? woffR : woffL);
    float* X = side ? g_ro : g_lo;
    const float* bias = side ? bR : bL;
    const float* gam = side ? gamR : gamL;

    float c[4][NR][4];
#pragma unroll
    for (int i = 0; i < 4; i++)
#pragma unroll
        for (int j = 0; j < NR; j++)
#pragma unroll
            for (int q = 0; q < 4; q++) c[i][j][q] = 0.f;

    auto loadStage = [&](int kt, int s) {
        const int k0 = kt * 32;
        uint32_t base = sbase + (uint32_t)s * STAGE_B;
#pragma unroll
        for (int i = 0; i < LS; i++) {
            int ch = tid + i * NT;
            int ar = ch >> 2, ac = ch & 3;
            cp_async16(base + ar * 80 + ac * 16, A + (size_t)ar * H_ + k0 + ac * 8);
            int br = ch >> 4, bc = ch & 15;
            cp_async16(base + A_STAGE_B + br * 272 + bc * 16,
                       Wm + (size_t)(k0 + br) * H_ + n0 + bc * 8);
        }
        CP_COMMIT();
    };

    loadStage(0, 0);
    if (KT > 1) loadStage(1, 1);
    if (KT > 2) loadStage(2, 2);

    for (int kt = 0; kt < KT; kt++) {
        int rem = KT - 1 - kt;
        if (rem >= 2) cp_wait<2>();
        else if (rem == 1) cp_wait<1>();
        else cp_wait<0>();
        __syncthreads();
        if (kt + 3 < KT) loadStage(kt + 3, (kt + 3) % STAGES);

        const uint32_t a_base = sbase + (uint32_t)((kt % STAGES) * STAGE_B);
        const uint32_t b_base = a_base + A_STAGE_B;
#pragma unroll
        for (int ks = 0; ks < 2; ks++) {
            uint32_t a[4][4], bb2[NP][4];
#pragma unroll
            for (int mr = 0; mr < 4; mr++)
                ldm_x4(a[mr], a_base + (warpM * 64 + mr * 16 + lane15) * 80
                                 + ks * 32 + laneHi * 16);
#pragma unroll
            for (int np = 0; np < NP; np++)
                ldm_x4_t(bb2[np], b_base + (ks * 16 + lane15) * 272
                                    + (warpN * TNW + np * 16 + laneHi * 8) * 2);
#pragma unroll
            for (int mr = 0; mr < 4; mr++)
#pragma unroll
                for (int np = 0; np < NP; np++) {
                    mma_f16(c[mr][2 * np + 0], a[mr], bb2[np][0], bb2[np][1]);
                    mma_f16(c[mr][2 * np + 1], a[mr], bb2[np][2], bb2[np][3]);
                }
        }
    }

    __half* uSide = g_u + (size_t)side * BS_ * H_;

    // ============== MODE 0: fragment epilogue (unchanged) ==============
    if (MODE == 0) {
        const int colbase = n0 + warpN * TNW + t4 * 2;
        float* statsDst = g_stats + (size_t)side * BS_ * 2;
#pragma unroll
        for (int mr = 0; mr < 4; mr++) {
#pragma unroll
            for (int hh = 0; hh < 2; hh++) {
                size_t r = m0 + warpM * 64 + mr * 16 + gid + hh * 8;
                float* xrow = X + r * H_;
                float s = 0.f, sq = 0.f;
#pragma unroll
                for (int nr = 0; nr < NR; nr++) {
                    int col = colbase + nr * 8;
                    float2 bv = *(const float2*)(bias + col);
                    float v0 = fmaxf(c[mr][nr][hh * 2 + 0] + bv.x, 0.f);
                    float v1 = fmaxf(c[mr][nr][hh * 2 + 1] + bv.y, 0.f);
                    *(float2*)(xrow + col) = make_float2(v0, v1);
                    float2 gv = *(const float2*)(gam + col);
                    *(__half2*)(uSide + r * H_ + col) =
                        __floats2half2_rn(v0 * gv.x, v1 * gv.y);
                    s += v0 + v1;
                    sq += v0 * v0 + v1 * v1;
                }
                s += __shfl_xor_sync(0xffffffffu, s, 1);
                sq += __shfl_xor_sync(0xffffffffu, sq, 1);
                s += __shfl_xor_sync(0xffffffffu, s, 2);
                sq += __shfl_xor_sync(0xffffffffu, sq, 2);
                if (t4 == 0) {
                    atomicAdd(statsDst + r * 2, s);
                    atomicAdd(statsDst + r * 2 + 1, sq);
                }
            }
        }
        return;
    }

    // ============== MODE 1/2: smem-staged, coalesced epilogue ============
    __syncthreads();
    float* sm = (float*)smraw;
#pragma unroll
    for (int mr = 0; mr < 4; mr++)
#pragma unroll
        for (int hh = 0; hh < 2; hh++) {
            int row = warpM * 64 + mr * 16 + gid + hh * 8;
#pragma unroll
            for (int nr = 0; nr < NR; nr++) {
                int col = warpN * TNW + nr * 8 + t4 * 2;
                *(float2*)&sm[row * 132 + col] =
                    make_float2(c[mr][nr][hh * 2 + 0], c[mr][nr][hh * 2 + 1]);
            }
        }
    __syncthreads();

    const int c0 = lane * 4;

    if (MODE == 1) {
        const int cb = (qp_base + side) * H_;
        const float* stats = g_stats + (size_t)(ln_phase + side) * BS_ * 2;
        __half* hSide = g_h + (size_t)side * BS_ * H_;
        const float4 q4 = *(const float4*)(g_q + cb + n0 + c0);
        const float4 p4 = *(const float4*)(g_p + cb + n0 + c0);
        for (int rr = wid; rr < 128; rr += WARPS) {
            size_t r = m0 + rr;
            float4 a4 = *(float4*)&sm[rr * 132 + c0];
            float2 st = *(const float2*)(stats + r * 2);
            float mu = st.x * (1.0f / H_);
            float var = st.y * (1.0f / H_) - mu * mu;
            float rstd = rsqrtf(fmaxf(var, 0.f) + 1e-5f);
            float mt = -rstd * mu;
            float v0 = fmaxf(fmaf(rstd, a4.x, fmaf(mt, q4.x, p4.x)), 0.f);
            float v1 = fmaxf(fmaf(rstd, a4.y, fmaf(mt, q4.y, p4.y)), 0.f);
            float v2 = fmaxf(fmaf(rstd, a4.z, fmaf(mt, q4.z, p4.z)), 0.f);
            float v3 = fmaxf(fmaf(rstd, a4.w, fmaf(mt, q4.w, p4.w)), 0.f);
            __half2 h[2] = {__floats2half2_rn(v0, v1), __floats2half2_rn(v2, v3)};
            *(uint2*)(hSide + r * H_ + n0 + c0) = *(uint2*)h;
        }
        return;
    }

    // MODE 2
    const float4 b4 = *(const float4*)(bias + n0 + c0);
    float4 g4v = make_float4(0.f, 0.f, 0.f, 0.f);
    if (statsPhase >= 0) g4v = *(const float4*)(gam + n0 + c0);
    float* statsDst = (statsPhase >= 0)
        ? g_stats + (size_t)(statsPhase + side) * BS_ * 2 : (float*)0;

    for (int rr = wid; rr < 128; rr += WARPS) {
        size_t r = m0 + rr;
        float4 a4 = *(float4*)&sm[rr * 132 + c0];
        float4 res = *(const float4*)(X + r * H_ + n0 + c0);
        float v0 = a4.x + b4.x + res.x;
        float v1 = a4.y + b4.y + res.y;
        float v2 = a4.z + b4.z + res.z;
        float v3 = a4.w + b4.w + res.w;
        size_t bi = r >> 11, si = r & 2047;
        int ocol = side * H_ + n0 + c0;
        *(float4*)(outA + (si * B_ + bi) * (size_t)(2 * H_) + ocol) =
            make_float4(v0, v1, v2, v3);
        if (outL)
            *(float4*)(outL + (bi * S_ + si) * (size_t)(2 * H_) + ocol) =
                make_float4(v0, v1, v2, v3);
        if (statsDst) {
            *(float4*)(X + r * H_ + n0 + c0) = make_float4(v0, v1, v2, v3);
            __half2 h[2] = {__floats2half2_rn(v0 * g4v.x, v1 * g4v.y),
                            __floats2half2_rn(v2 * g4v.z, v3 * g4v.w)};
            *(uint2*)(uSide + r * H_ + n0 + c0) = *(uint2*)h;
            float s = v0 + v1 + v2 + v3;
            float sq = v0 * v0 + v1 * v1 + v2 * v2 + v3 * v3;
#pragma unroll
            for (int o = 16; o; o >>= 1) {
                s += __shfl_xor_sync(0xffffffffu, s, o);
                sq += __shfl_xor_sync(0xffffffffu, sq, o);
            }
            if (lane == 0) {
                atomicAdd(statsDst + r * 2, s);
                atomicAdd(statsDst + r * 2 + 1, sq);
            }
        }
    }
}

// ---------------------------------------------------------------------------
extern "C" void kernel_launch(void* const* d_in, const int* in_sizes, int n_in,
                              void* d_out, int out_size) {
    const float* inputs = (const float*)d_in[0];
    const float* lp     = (const float*)d_in[1];
    const float* rp     = (const float*)d_in[2];
    const float* Wl     = (const float*)d_in[3];
    const float* bl     = (const float*)d_in[4];
    const float* Wr     = (const float*)d_in[5];
    const float* br     = (const float*)d_in[6];
    const float* lw1    = (const float*)d_in[7];
    const float* lb1    = (const float*)d_in[8];
    const float* lw2    = (const float*)d_in[9];
    const float* lb2    = (const float*)d_in[10];
    const float* lg     = (const float*)d_in[11];
    const float* lbeta  = (const float*)d_in[12];
    const float* rw1    = (const float*)d_in[13];
    const float* rb1    = (const float*)d_in[14];
    const float* rw2    = (const float*)d_in[15];
    const float* rb2    = (const float*)d_in[16];
    const float* rg     = (const float*)d_in[17];
    const float* rbeta  = (const float*)d_in[18];
    float* out = (float*)d_out;
    (void)in_sizes; (void)n_in; (void)out_size;

    cudaFuncSetAttribute(tc_gemm<0, 64, 128>,
                         cudaFuncAttributeMaxDynamicSharedMemorySize, SMEM_BYTES);
    cudaFuncSetAttribute(tc_gemm<1, 16, 256>,
                         cudaFuncAttributeMaxDynamicSharedMemorySize, SMEM_BYTES);
    cudaFuncSetAttribute(tc_gemm<2, 16, 256>,
                         cudaFuncAttributeMaxDynamicSharedMemorySize, SMEM_BYTES);

    // 1) single merged prep: pad + f2h + q/p + stats zero
    prep_all<<<PAD_BLK + F2H_BLK + QP_BLK + ZERO_BLK, 256>>>(
        inputs, lp, rp, Wl, Wr, lw1, lw2, rw1, rw2,
        lg, rg, lbeta, lb1, rbeta, rb1);

    // 2) wide projections, L+R merged (128 threads, 64x64 warp tiles)
    tc_gemm<0, 64, 128><<<dim3(4, 16, 32), 128, SMEM_BYTES>>>(
        OFF_WL, OFF_WR, bl, br, lg, rg, 0, 0, 0, nullptr, nullptr);

    // 3) residual FF layers, L+R merged (256 threads, 64x32 warp tiles)
    for (int i = 0; i < L_; i++) {
        bool last = (i == L_ - 1);
        tc_gemm<1, 16, 256><<<dim3(4, 256, 2), 256, SMEM_BYTES>>>(
            OFF_LW1 + i * 262144, OFF_RW1 + i * 262144,
            nullptr, nullptr, nullptr, nullptr,
            i * 2, -1, (i == 0) ? 0 : 2, nullptr, nullptr);

        float* oall = out + (size_t)i * S_ * B_ * 2 * H_;
        float* olast = last ? out + (size_t)L_ * S_ * B_ * 2 * H_ : nullptr;
        tc_gemm<2, 16, 256><<<dim3(4, 256, 2), 256, SMEM_BYTES>>>(
            OFF_LW2 + i * 262144, OFF_RW2 + i * 262144,
            lb2 + (size_t)i * H_, rb2 + (size_t)i * H_,
            last ? nullptr : lg + (size_t)(i + 1) * H_,
            last ? nullptr : rg + (size_t)(i + 1) * H_,
            0, last ? -1 : 2, 0, oall, olast);
    }
}

// round 16
// speedup vs baseline: 1.5220x; 1.0409x over previous
#include <cuda_runtime.h>
#include <cuda_fp16.h>
#include <cstdint>

#define B_ 16
#define S_ 2048
#define H_ 512
#define W_ 4
#define L_ 2
#define SP_ (S_ + 2 * W_)   // 2056
#define BS_ (B_ * S_)       // 32768

// ---------------------------------------------------------------------------
// Scratch (__device__ globals; allocation-free rule)
// ---------------------------------------------------------------------------
__device__ __align__(256) __half g_pad_h[B_ * SP_ * H_];   // fp16 padded input
__device__ __align__(256) __half g_xh[2 * BS_ * H_];       // fp16 residual stream per side
__device__ __align__(256) __half g_h[2 * BS_ * H_];        // fp16 hidden per side
__device__ __align__(256) float  g_stats[4 * BS_ * 2];     // (sum, sumsq) x 4 phases
__device__ __align__(256) float  g_q[4 * H_];              // gamma @ W1 per (layer,side)
__device__ __align__(256) float  g_p[4 * H_];              // beta @ W1 + b1
// fp16 weights; W1 blocks row-scaled by gamma. Linear layout:
#define OFF_WL  0
#define OFF_WR  1048576
#define OFF_LW1 2097152
#define OFF_LW2 2621440
#define OFF_RW1 3145728
#define OFF_RW2 3670016
__device__ __align__(256) __half g_wh[4194304];

// ---------------------------------------------------------------------------
// PTX helpers
// ---------------------------------------------------------------------------
__device__ __forceinline__ uint32_t smem_u32(const void* p) {
    uint32_t a;
    asm("{ .reg .u64 t; cvta.to.shared.u64 t, %1; cvt.u32.u64 %0, t; }" : "=r"(a) : "l"(p));
    return a;
}
__device__ __forceinline__ void cp_async16(uint32_t dst, const void* src) {
    asm volatile("cp.async.cg.shared.global [%0], [%1], 16;" :: "r"(dst), "l"(src) : "memory");
}
template <int N>
__device__ __forceinline__ void cp_wait() {
    asm volatile("cp.async.wait_group %0;" :: "n"(N) : "memory");
}
#define CP_COMMIT() asm volatile("cp.async.commit_group;" ::: "memory")

__device__ __forceinline__ void ldm_x4(uint32_t r[4], uint32_t addr) {
    asm volatile("ldmatrix.sync.aligned.m8n8.x4.shared.b16 {%0,%1,%2,%3}, [%4];"
        : "=r"(r[0]), "=r"(r[1]), "=r"(r[2]), "=r"(r[3]) : "r"(addr));
}
__device__ __forceinline__ void ldm_x4_t(uint32_t r[4], uint32_t addr) {
    asm volatile("ldmatrix.sync.aligned.m8n8.x4.trans.shared.b16 {%0,%1,%2,%3}, [%4];"
        : "=r"(r[0]), "=r"(r[1]), "=r"(r[2]), "=r"(r[3]) : "r"(addr));
}
__device__ __forceinline__ void mma_f16(float c[4], const uint32_t a[4],
                                        uint32_t b0, uint32_t b1) {
    asm volatile(
        "mma.sync.aligned.m16n8k16.row.col.f32.f16.f16.f32 "
        "{%0,%1,%2,%3}, {%4,%5,%6,%7}, {%8,%9}, {%0,%1,%2,%3};"
        : "+f"(c[0]), "+f"(c[1]), "+f"(c[2]), "+f"(c[3])
        : "r"(a[0]), "r"(a[1]), "r"(a[2]), "r"(a[3]), "r"(b0), "r"(b1));
}

// ---------------------------------------------------------------------------
// One prep kernel: [pad | f2h(gamma folded into W1) | q/p GEMV | zero stats]
// ---------------------------------------------------------------------------
constexpr int PAD_BLK = 16448;   // B_*SP_*(H_/4)/256
constexpr int F2H_BLK = 2048;    // 524288 uint4 / 256
constexpr int QP_BLK = 8;        // 4 combos * 512 cols / 256
constexpr int ZERO_BLK = 256;    // 65536 float4 / 256

__global__ void prep_all(const float* __restrict__ inp, const float* __restrict__ lp,
                         const float* __restrict__ rp,
                         const float* __restrict__ Wl, const float* __restrict__ Wr,
                         const float* __restrict__ lw1, const float* __restrict__ lw2,
                         const float* __restrict__ rw1, const float* __restrict__ rw2,
                         const float* __restrict__ lg, const float* __restrict__ rg,
                         const float* __restrict__ lbeta, const float* __restrict__ lb1,
                         const float* __restrict__ rbeta, const float* __restrict__ rb1) {
    int blk = blockIdx.x;
    int tid = threadIdx.x;
    if (blk < PAD_BLK) {
        const int H4 = H_ / 4;
        int idx = blk * 256 + tid;
        int h4 = idx % H4;
        int t = idx / H4;
        int p = t % SP_;
        int b = t / SP_;
        float4 v;
        if (p < W_) v = ((const float4*)lp)[p * H4 + h4];
        else if (p < W_ + S_) v = ((const float4*)inp)[((size_t)b * S_ + (p - W_)) * H4 + h4];
        else v = ((const float4*)rp)[(p - W_ - S_) * H4 + h4];
        __half2 h[2];
        h[0] = __floats2half2_rn(v.x, v.y);
        h[1] = __floats2half2_rn(v.z, v.w);
        ((uint2*)g_pad_h)[idx] = *(uint2*)h;
        return;
    }
    blk -= PAD_BLK;
    if (blk < F2H_BLK) {
        // fp32 -> fp16 weights; W1 rows scaled by gamma[k] (LN fold)
        int i = blk * 256 + tid;   // uint4 index (8 halves)
        const float* src;
        int off;
        float scale = 1.0f;
        if (i < 131072)      { src = Wl;  off = i; }
        else if (i < 262144) { src = Wr;  off = i - 131072; }
        else if (i < 327680) {
            src = lw1; off = i - 262144;
            scale = lg[(off >> 15) * H_ + (((off & 32767) * 8) >> 9)];
        }
        else if (i < 393216) { src = lw2; off = i - 327680; }
        else if (i < 458752) {
            src = rw1; off = i - 393216;
            scale = rg[(off >> 15) * H_ + (((off & 32767) * 8) >> 9)];
        }
        else                 { src = rw2; off = i - 458752; }
        float4 v0 = ((const float4*)src)[2 * off];
        float4 v1 = ((const float4*)src)[2 * off + 1];
        __half2 h[4];
        h[0] = __floats2half2_rn(v0.x * scale, v0.y * scale);
        h[1] = __floats2half2_rn(v0.z * scale, v0.w * scale);
        h[2] = __floats2half2_rn(v1.x * scale, v1.y * scale);
        h[3] = __floats2half2_rn(v1.z * scale, v1.w * scale);
        ((uint4*)g_wh)[i] = *(uint4*)h;
        return;
    }
    blk -= F2H_BLK;
    if (blk < QP_BLK) {
        int jj = blk * 256 + tid;
        int combo = jj >> 9;
        int j = jj & 511;
        int layer = combo >> 1, side = combo & 1;
        const float* Wm = (side ? rw1 : lw1) + (size_t)layer * H_ * H_;
        const float* ga = (side ? rg : lg) + layer * H_;
        const float* be = (side ? rbeta : lbeta) + layer * H_;
        const float* b1 = (side ? rb1 : lb1) + layer * H_;
        float q = 0.f, p = 0.f;
        for (int k = 0; k < H_; k++) {
            float w = Wm[(size_t)k * H_ + j];
            q += ga[k] * w;
            p += be[k] * w;
        }
        g_q[combo * H_ + j] = q;
        g_p[combo * H_ + j] = p + b1[j];
        return;
    }
    blk -= QP_BLK;
    ((float4*)g_stats)[blk * 256 + tid] = make_float4(0.f, 0.f, 0.f, 0.f);
}

// ---------------------------------------------------------------------------
// fp16 mma.sync GEMM: 128x128 CTA tile, BK=32, 4-stage cp.async, single
// __syncthreads per chunk.
//   MODE 0: NT=128, 2x2 warps, 64x64 tiles; fragment epilogue (reg-sacred);
//           relu(acc+b) -> g_xh fp16, stats phase side.
//   MODE 1: NT=256, 2x4 warps, 64x32 tiles; staged epilogue;
//           A = g_xh (gamma pre-folded in W1); v = rstd*acc - rstd*mu*q + p,
//           relu -> g_h fp16.
//   MODE 2: NT=256, staged epilogue; A = g_h; v = fp32(xh) + acc + b2
//           -> out_all (+out_last) fp32 at col side*H_. If not last:
//           g_xh = fp16(v), stats phase 2+side.
// ---------------------------------------------------------------------------
constexpr int A_STAGE_B = 128 * 80;
constexpr int B_STAGE_B = 32 * 272;
constexpr int STAGE_B = A_STAGE_B + B_STAGE_B;  // 18944 B
constexpr int STAGES = 4;
constexpr int SMEM_BYTES = STAGES * STAGE_B;    // 75776 B (>= 128*132*4)

template <int MODE, int KT, int NT>
__global__ void __launch_bounds__(NT, 2)
tc_gemm(int woffL, int woffR,
        const float* __restrict__ bL, const float* __restrict__ bR,
        int qp_base, int statsPhase, int ln_phase,
        float* __restrict__ outA, float* __restrict__ outL) {
    constexpr int WNC = NT / 64;
    constexpr int TNW = 128 / WNC;
    constexpr int NP = TNW / 16;
    constexpr int NR = 2 * NP;
    constexpr int LS = 512 / NT;
    constexpr int WARPS = NT / 32;

    extern __shared__ char smraw[];
    const uint32_t sbase = smem_u32(smraw);
    const int tid = threadIdx.x;
    const int lane = tid & 31, wid = tid >> 5;
    const int warpM = wid / WNC, warpN = wid % WNC;
    const int gid = lane >> 2, t4 = lane & 3;
    const int lane15 = lane & 15, laneHi = lane >> 4;
    const int n0 = blockIdx.x * 128;

    int side;
    size_t m0;
    const __half* A;
    if (MODE == 0) {
        side = blockIdx.z >> 4;
        int bb = blockIdx.z & 15;
        m0 = (size_t)bb * S_ + blockIdx.y * 128;
        A = g_pad_h + ((size_t)bb * SP_ + blockIdx.y * 128 + side * (W_ + 1)) * H_;
    } else {
        side = blockIdx.z;
        m0 = (size_t)blockIdx.y * 128;
        A = (MODE == 1 ? g_xh : g_h) + ((size_t)side * BS_ + m0) * H_;
    }
    const __half* Wm = g_wh + (side ? woffR : woffL);
    const float* bias = side ? bR : bL;

    float c[4][NR][4];
#pragma unroll
    for (int i = 0; i < 4; i++)
#pragma unroll
        for (int j = 0; j < NR; j++)
#pragma unroll
            for (int q = 0; q < 4; q++) c[i][j][q] = 0.f;

    auto loadStage = [&](int kt, int s) {
        const int k0 = kt * 32;
        uint32_t base = sbase + (uint32_t)s * STAGE_B;
#pragma unroll
        for (int i = 0; i < LS; i++) {
            int ch = tid + i * NT;
            int ar = ch >> 2, ac = ch & 3;
            cp_async16(base + ar * 80 + ac * 16, A + (size_t)ar * H_ + k0 + ac * 8);
            int br = ch >> 4, bc = ch & 15;
            cp_async16(base + A_STAGE_B + br * 272 + bc * 16,
                       Wm + (size_t)(k0 + br) * H_ + n0 + bc * 8);
        }
        CP_COMMIT();
    };

    loadStage(0, 0);
    if (KT > 1) loadStage(1, 1);
    if (KT > 2) loadStage(2, 2);

    for (int kt = 0; kt < KT; kt++) {
        int rem = KT - 1 - kt;
        if (rem >= 2) cp_wait<2>();
        else if (rem == 1) cp_wait<1>();
        else cp_wait<0>();
        __syncthreads();
        if (kt + 3 < KT) loadStage(kt + 3, (kt + 3) % STAGES);

        const uint32_t a_base = sbase + (uint32_t)((kt % STAGES) * STAGE_B);
        const uint32_t b_base = a_base + A_STAGE_B;
#pragma unroll
        for (int ks = 0; ks < 2; ks++) {
            uint32_t a[4][4], bb2[NP][4];
#pragma unroll
            for (int mr = 0; mr < 4; mr++)
                ldm_x4(a[mr], a_base + (warpM * 64 + mr * 16 + lane15) * 80
                                 + ks * 32 + laneHi * 16);
#pragma unroll
            for (int np = 0; np < NP; np++)
                ldm_x4_t(bb2[np], b_base + (ks * 16 + lane15) * 272
                                    + (warpN * TNW + np * 16 + laneHi * 8) * 2);
#pragma unroll
            for (int mr = 0; mr < 4; mr++)
#pragma unroll
                for (int np = 0; np < NP; np++) {
                    mma_f16(c[mr][2 * np + 0], a[mr], bb2[np][0], bb2[np][1]);
                    mma_f16(c[mr][2 * np + 1], a[mr], bb2[np][2], bb2[np][3]);
                }
        }
    }

    __half* xhSide = g_xh + (size_t)side * BS_ * H_;

    // ============== MODE 0: fragment epilogue (reg-sacred shape) ==============
    if (MODE == 0) {
        const int colbase = n0 + warpN * TNW + t4 * 2;
        float* statsDst = g_stats + (size_t)side * BS_ * 2;
#pragma unroll
        for (int mr = 0; mr < 4; mr++) {
#pragma unroll
            for (int hh = 0; hh < 2; hh++) {
                size_t r = m0 + warpM * 64 + mr * 16 + gid + hh * 8;
                __half* xrow = xhSide + r * H_;
                float s = 0.f, sq = 0.f;
#pragma unroll
                for (int nr = 0; nr < NR; nr++) {
                    int col = colbase + nr * 8;
                    float2 bv = *(const float2*)(bias + col);
                    float v0 = fmaxf(c[mr][nr][hh * 2 + 0] + bv.x, 0.f);
                    float v1 = fmaxf(c[mr][nr][hh * 2 + 1] + bv.y, 0.f);
                    *(__half2*)(xrow + col) = __floats2half2_rn(v0, v1);
                    s += v0 + v1;
                    sq += v0 * v0 + v1 * v1;
                }
                s += __shfl_xor_sync(0xffffffffu, s, 1);
                sq += __shfl_xor_sync(0xffffffffu, sq, 1);
                s += __shfl_xor_sync(0xffffffffu, s, 2);
                sq += __shfl_xor_sync(0xffffffffu, sq, 2);
                if (t4 == 0) {
                    atomicAdd(statsDst + r * 2, s);
                    atomicAdd(statsDst + r * 2 + 1, sq);
                }
            }
        }
        return;
    }

    // ============== MODE 1/2: smem-staged, coalesced epilogue ============
    __syncthreads();
    float* sm = (float*)smraw;
#pragma unroll
    for (int mr = 0; mr < 4; mr++)
#pragma unroll
        for (int hh = 0; hh < 2; hh++) {
            int row = warpM * 64 + mr * 16 + gid + hh * 8;
#pragma unroll
            for (int nr = 0; nr < NR; nr++) {
                int col = warpN * TNW + nr * 8 + t4 * 2;
                *(float2*)&sm[row * 132 + col] =
                    make_float2(c[mr][nr][hh * 2 + 0], c[mr][nr][hh * 2 + 1]);
            }
        }
    __syncthreads();

    const int c0 = lane * 4;   // one warp per row; lane covers cols 4l..4l+3

    if (MODE == 1) {
        const int cb = (qp_base + side) * H_;
        const float* stats = g_stats + (size_t)(ln_phase + side) * BS_ * 2;
        __half* hSide = g_h + (size_t)side * BS_ * H_;
        const float4 q4 = *(const float4*)(g_q + cb + n0 + c0);
        const float4 p4 = *(const float4*)(g_p + cb + n0 + c0);
        for (int rr = wid; rr < 128; rr += WARPS) {
            size_t r = m0 + rr;
            float4 a4 = *(float4*)&sm[rr * 132 + c0];
            float2 st = *(const float2*)(stats + r * 2);
            float mu = st.x * (1.0f / H_);
            float var = st.y * (1.0f / H_) - mu * mu;
            float rstd = rsqrtf(fmaxf(var, 0.f) + 1e-5f);
            float mt = -rstd * mu;
            float v0 = fmaxf(fmaf(rstd, a4.x, fmaf(mt, q4.x, p4.x)), 0.f);
            float v1 = fmaxf(fmaf(rstd, a4.y, fmaf(mt, q4.y, p4.y)), 0.f);
            float v2 = fmaxf(fmaf(rstd, a4.z, fmaf(mt, q4.z, p4.z)), 0.f);
            float v3 = fmaxf(fmaf(rstd, a4.w, fmaf(mt, q4.w, p4.w)), 0.f);
            __half2 h[2] = {__floats2half2_rn(v0, v1), __floats2half2_rn(v2, v3)};
            *(uint2*)(hSide + r * H_ + n0 + c0) = *(uint2*)h;
        }
        return;
    }

    // MODE 2
    const float4 b4 = *(const float4*)(bias + n0 + c0);
    float* statsDst = (statsPhase >= 0)
        ? g_stats + (size_t)(statsPhase + side) * BS_ * 2 : (float*)0;

    for (int rr = wid; rr < 128; rr += WARPS) {
        size_t r = m0 + rr;
        float4 a4 = *(float4*)&sm[rr * 132 + c0];
        uint2 rh = *(const uint2*)(xhSide + r * H_ + n0 + c0);
        float2 r01 = __half22float2(*(__half2*)&rh.x);
        float2 r23 = __half22float2(*(__half2*)&rh.y);
        float v0 = a4.x + b4.x + r01.x;
        float v1 = a4.y + b4.y + r01.y;
        float v2 = a4.z + b4.z + r23.x;
        float v3 = a4.w + b4.w + r23.y;
        size_t bi = r >> 11, si = r & 2047;
        int ocol = side * H_ + n0 + c0;
        *(float4*)(outA + (si * B_ + bi) * (size_t)(2 * H_) + ocol) =
            make_float4(v0, v1, v2, v3);
        if (outL)
            *(float4*)(outL + (bi * S_ + si) * (size_t)(2 * H_) + ocol) =
                make_float4(v0, v1, v2, v3);
        if (statsDst) {
            __half2 h[2] = {__floats2half2_rn(v0, v1), __floats2half2_rn(v2, v3)};
            *(uint2*)(xhSide + r * H_ + n0 + c0) = *(uint2*)h;
            float s = v0 + v1 + v2 + v3;
            float sq = v0 * v0 + v1 * v1 + v2 * v2 + v3 * v3;
#pragma unroll
            for (int o = 16; o; o >>= 1) {
                s += __shfl_xor_sync(0xffffffffu, s, o);
                sq += __shfl_xor_sync(0xffffffffu, sq, o);
            }
            if (lane == 0) {
                atomicAdd(statsDst + r * 2, s);
                atomicAdd(statsDst + r * 2 + 1, sq);
            }
        }
    }
}

// ---------------------------------------------------------------------------
extern "C" void kernel_launch(void* const* d_in, const int* in_sizes, int n_in,
                              void* d_out, int out_size) {
    const float* inputs = (const float*)d_in[0];
    const float* lp     = (const float*)d_in[1];
    const float* rp     = (const float*)d_in[2];
    const float* Wl     = (const float*)d_in[3];
    const float* bl     = (const float*)d_in[4];
    const float* Wr     = (const float*)d_in[5];
    const float* br     = (const float*)d_in[6];
    const float* lw1    = (const float*)d_in[7];
    const float* lb1    = (const float*)d_in[8];
    const float* lw2    = (const float*)d_in[9];
    const float* lb2    = (const float*)d_in[10];
    const float* lg     = (const float*)d_in[11];
    const float* lbeta  = (const float*)d_in[12];
    const float* rw1    = (const float*)d_in[13];
    const float* rb1    = (const float*)d_in[14];
    const float* rw2    = (const float*)d_in[15];
    const float* rb2    = (const float*)d_in[16];
    const float* rg     = (const float*)d_in[17];
    const float* rbeta  = (const float*)d_in[18];
    float* out = (float*)d_out;
    (void)in_sizes; (void)n_in; (void)out_size;

    cudaFuncSetAttribute(tc_gemm<0, 64, 128>,
                         cudaFuncAttributeMaxDynamicSharedMemorySize, SMEM_BYTES);
    cudaFuncSetAttribute(tc_gemm<1, 16, 256>,
                         cudaFuncAttributeMaxDynamicSharedMemorySize, SMEM_BYTES);
    cudaFuncSetAttribute(tc_gemm<2, 16, 256>,
                         cudaFuncAttributeMaxDynamicSharedMemorySize, SMEM_BYTES);

    // 1) single merged prep: pad + f2h(gamma fold) + q/p + stats zero
    prep_all<<<PAD_BLK + F2H_BLK + QP_BLK + ZERO_BLK, 256>>>(
        inputs, lp, rp, Wl, Wr, lw1, lw2, rw1, rw2,
        lg, rg, lbeta, lb1, rbeta, rb1);

    // 2) wide projections, L+R merged
    tc_gemm<0, 64, 128><<<dim3(4, 16, 32), 128, SMEM_BYTES>>>(
        OFF_WL, OFF_WR, bl, br, 0, 0, 0, nullptr, nullptr);

    // 3) residual FF layers, L+R merged
    for (int i = 0; i < L_; i++) {
        bool last = (i == L_ - 1);
        tc_gemm<1, 16, 256><<<dim3(4, 256, 2), 256, SMEM_BYTES>>>(
            OFF_LW1 + i * 262144, OFF_RW1 + i * 262144,
            nullptr, nullptr,
            i * 2, -1, (i == 0) ? 0 : 2, nullptr, nullptr);

        float* oall = out + (size_t)i * S_ * B_ * 2 * H_;
        float* olast = last ? out + (size_t)L_ * S_ * B_ * 2 * H_ : nullptr;
        tc_gemm<2, 16, 256><<<dim3(4, 256, 2), 256, SMEM_BYTES>>>(
            OFF_LW2 + i * 262144, OFF_RW2 + i * 262144,
            lb2 + (size_t)i * H_, rb2 + (size_t)i * H_,
            0, last ? -1 : 2, 0, oall, olast);
    }
}

// round 17
// speedup vs baseline: 1.5598x; 1.0248x over previous
#include <cuda_runtime.h>
#include <cuda_fp16.h>
#include <cstdint>

#define B_ 16
#define S_ 2048
#define H_ 512
#define W_ 4
#define L_ 2
#define SP_ (S_ + 2 * W_)   // 2056
#define BS_ (B_ * S_)       // 32768

// ---------------------------------------------------------------------------
// Scratch (__device__ globals; allocation-free rule)
// ---------------------------------------------------------------------------
__device__ __align__(256) __half g_pad_h[B_ * SP_ * H_];   // fp16 padded input
__device__ __align__(256) __half g_xh[2 * BS_ * H_];       // fp16 residual stream per side
__device__ __align__(256) __half g_h[2 * BS_ * H_];        // fp16 hidden per side
__device__ __align__(256) float  g_stats[4 * BS_ * 2];     // (sum, sumsq) x 4 phases
__device__ __align__(256) float  g_q[4 * H_];              // gamma @ W1 per (layer,side)
__device__ __align__(256) float  g_p[4 * H_];              // beta @ W1 + b1
// fp16 weights; W1 blocks row-scaled by gamma. Linear layout:
#define OFF_WL  0
#define OFF_WR  1048576
#define OFF_LW1 2097152
#define OFF_LW2 2621440
#define OFF_RW1 3145728
#define OFF_RW2 3670016
__device__ __align__(256) __half g_wh[4194304];

// ---------------------------------------------------------------------------
// PTX helpers
// ---------------------------------------------------------------------------
__device__ __forceinline__ uint32_t smem_u32(const void* p) {
    uint32_t a;
    asm("{ .reg .u64 t; cvta.to.shared.u64 t, %1; cvt.u32.u64 %0, t; }" : "=r"(a) : "l"(p));
    return a;
}
__device__ __forceinline__ void cp_async16(uint32_t dst, const void* src) {
    asm volatile("cp.async.cg.shared.global [%0], [%1], 16;" :: "r"(dst), "l"(src) : "memory");
}
template <int N>
__device__ __forceinline__ void cp_wait() {
    asm volatile("cp.async.wait_group %0;" :: "n"(N) : "memory");
}
#define CP_COMMIT() asm volatile("cp.async.commit_group;" ::: "memory")

__device__ __forceinline__ void ldm_x4(uint32_t r[4], uint32_t addr) {
    asm volatile("ldmatrix.sync.aligned.m8n8.x4.shared.b16 {%0,%1,%2,%3}, [%4];"
        : "=r"(r[0]), "=r"(r[1]), "=r"(r[2]), "=r"(r[3]) : "r"(addr));
}
__device__ __forceinline__ void ldm_x4_t(uint32_t r[4], uint32_t addr) {
    asm volatile("ldmatrix.sync.aligned.m8n8.x4.trans.shared.b16 {%0,%1,%2,%3}, [%4];"
        : "=r"(r[0]), "=r"(r[1]), "=r"(r[2]), "=r"(r[3]) : "r"(addr));
}
__device__ __forceinline__ void mma_f16(float c[4], const uint32_t a[4],
                                        uint32_t b0, uint32_t b1) {
    asm volatile(
        "mma.sync.aligned.m16n8k16.row.col.f32.f16.f16.f32 "
        "{%0,%1,%2,%3}, {%4,%5,%6,%7}, {%8,%9}, {%0,%1,%2,%3};"
        : "+f"(c[0]), "+f"(c[1]), "+f"(c[2]), "+f"(c[3])
        : "r"(a[0]), "r"(a[1]), "r"(a[2]), "r"(a[3]), "r"(b0), "r"(b1));
}

// ---------------------------------------------------------------------------
// One prep kernel: [pad | f2h(gamma folded into W1) | q/p GEMV | zero stats]
// ---------------------------------------------------------------------------
constexpr int PAD_BLK = 16448;
constexpr int F2H_BLK = 2048;
constexpr int QP_BLK = 8;
constexpr int ZERO_BLK = 256;

__global__ void prep_all(const float* __restrict__ inp, const float* __restrict__ lp,
                         const float* __restrict__ rp,
                         const float* __restrict__ Wl, const float* __restrict__ Wr,
                         const float* __restrict__ lw1, const float* __restrict__ lw2,
                         const float* __restrict__ rw1, const float* __restrict__ rw2,
                         const float* __restrict__ lg, const float* __restrict__ rg,
                         const float* __restrict__ lbeta, const float* __restrict__ lb1,
                         const float* __restrict__ rbeta, const float* __restrict__ rb1) {
    int blk = blockIdx.x;
    int tid = threadIdx.x;
    if (blk < PAD_BLK) {
        const int H4 = H_ / 4;
        int idx = blk * 256 + tid;
        int h4 = idx % H4;
        int t = idx / H4;
        int p = t % SP_;
        int b = t / SP_;
        float4 v;
        if (p < W_) v = ((const float4*)lp)[p * H4 + h4];
        else if (p < W_ + S_) v = ((const float4*)inp)[((size_t)b * S_ + (p - W_)) * H4 + h4];
        else v = ((const float4*)rp)[(p - W_ - S_) * H4 + h4];
        __half2 h[2];
        h[0] = __floats2half2_rn(v.x, v.y);
        h[1] = __floats2half2_rn(v.z, v.w);
        ((uint2*)g_pad_h)[idx] = *(uint2*)h;
        return;
    }
    blk -= PAD_BLK;
    if (blk < F2H_BLK) {
        int i = blk * 256 + tid;
        const float* src;
        int off;
        float scale = 1.0f;
        if (i < 131072)      { src = Wl;  off = i; }
        else if (i < 262144) { src = Wr;  off = i - 131072; }
        else if (i < 327680) {
            src = lw1; off = i - 262144;
            scale = lg[(off >> 15) * H_ + (((off & 32767) * 8) >> 9)];
        }
        else if (i < 393216) { src = lw2; off = i - 327680; }
        else if (i < 458752) {
            src = rw1; off = i - 393216;
            scale = rg[(off >> 15) * H_ + (((off & 32767) * 8) >> 9)];
        }
        else                 { src = rw2; off = i - 458752; }
        float4 v0 = ((const float4*)src)[2 * off];
        float4 v1 = ((const float4*)src)[2 * off + 1];
        __half2 h[4];
        h[0] = __floats2half2_rn(v0.x * scale, v0.y * scale);
        h[1] = __floats2half2_rn(v0.z * scale, v0.w * scale);
        h[2] = __floats2half2_rn(v1.x * scale, v1.y * scale);
        h[3] = __floats2half2_rn(v1.z * scale, v1.w * scale);
        ((uint4*)g_wh)[i] = *(uint4*)h;
        return;
    }
    blk -= F2H_BLK;
    if (blk < QP_BLK) {
        int jj = blk * 256 + tid;
        int combo = jj >> 9;
        int j = jj & 511;
        int layer = combo >> 1, side = combo & 1;
        const float* Wm = (side ? rw1 : lw1) + (size_t)layer * H_ * H_;
        const float* ga = (side ? rg : lg) + layer * H_;
        const float* be = (side ? rbeta : lbeta) + layer * H_;
        const float* b1 = (side ? rb1 : lb1) + layer * H_;
        float q = 0.f, p = 0.f;
        for (int k = 0; k < H_; k++) {
            float w = Wm[(size_t)k * H_ + j];
            q += ga[k] * w;
            p += be[k] * w;
        }
        g_q[combo * H_ + j] = q;
        g_p[combo * H_ + j] = p + b1[j];
        return;
    }
    blk -= QP_BLK;
    ((float4*)g_stats)[blk * 256 + tid] = make_float4(0.f, 0.f, 0.f, 0.f);
}

// ---------------------------------------------------------------------------
// fp16 mma.sync GEMM: 128x128 CTA tile, BKT k-chunk, cp.async pipeline,
// single __syncthreads per chunk.
//   MODE 0: NT=128, 2x2 warps, 64x64 tiles, BKT=32, 4 stages (reg-sacred,
//           crossbar-bound config; unchanged from best). Fragment epilogue.
//   MODE 1/2: NT=256, 2x4 warps, 64x32 tiles, BKT=64, 3 stages — HALVES the
//           per-chunk sync/drain count (these launches are stall-bound, not
//           resource-bound). Smem-staged coalesced epilogue.
// ---------------------------------------------------------------------------
template <int MODE, int KT, int NT, int BKT>
__global__ void __launch_bounds__(NT, 2)
tc_gemm(int woffL, int woffR,
        const float* __restrict__ bL, const float* __restrict__ bR,
        int qp_base, int statsPhase, int ln_phase,
        float* __restrict__ outA, float* __restrict__ outL) {
    constexpr int WNC = NT / 64;
    constexpr int TNW = 128 / WNC;
    constexpr int NP = TNW / 16;
    constexpr int NR = 2 * NP;
    constexpr int WARPS = NT / 32;
    constexpr int KS = BKT / 16;                       // mma k-steps per chunk
    constexpr int AS = (BKT == 32) ? 80 : 144;          // A smem row stride (B)
    constexpr int A_STG = 128 * AS;
    constexpr int STG_B = A_STG + BKT * 272;
    constexpr int NSTAGE = (BKT == 32) ? 4 : 3;

    extern __shared__ char smraw[];
    const uint32_t sbase = smem_u32(smraw);
    const int tid = threadIdx.x;
    const int lane = tid & 31, wid = tid >> 5;
    const int warpM = wid / WNC, warpN = wid % WNC;
    const int gid = lane >> 2, t4 = lane & 3;
    const int lane15 = lane & 15, laneHi = lane >> 4;
    const int n0 = blockIdx.x * 128;

    int side;
    size_t m0;
    const __half* A;
    if (MODE == 0) {
        side = blockIdx.z >> 4;
        int bb = blockIdx.z & 15;
        m0 = (size_t)bb * S_ + blockIdx.y * 128;
        A = g_pad_h + ((size_t)bb * SP_ + blockIdx.y * 128 + side * (W_ + 1)) * H_;
    } else {
        side = blockIdx.z;
        m0 = (size_t)blockIdx.y * 128;
        A = (MODE == 1 ? g_xh : g_h) + ((size_t)side * BS_ + m0) * H_;
    }
    const __half* Wm = g_wh + (side ? woffR : woffL);
    const float* bias = side ? bR : bL;

    float c[4][NR][4];
#pragma unroll
    for (int i = 0; i < 4; i++)
#pragma unroll
        for (int j = 0; j < NR; j++)
#pragma unroll
            for (int q = 0; q < 4; q++) c[i][j][q] = 0.f;

    auto loadStage = [&](int kt, int s) {
        const int k0 = kt * BKT;
        uint32_t base = sbase + (uint32_t)s * STG_B;
#pragma unroll
        for (int i = 0; i < 4; i++) {       // A: 16*BKT 16B-chunks / NT == 4
            int ch = tid + i * NT;
            int ar, ac;
            if (BKT == 32) { ar = ch >> 2; ac = ch & 3; }
            else           { ar = ch >> 3; ac = ch & 7; }
            cp_async16(base + ar * AS + ac * 16, A + (size_t)ar * H_ + k0 + ac * 8);
            int br = ch >> 4, bc = ch & 15; // B: BKT*16 chunks / NT == 4
            cp_async16(base + A_STG + br * 272 + bc * 16,
                       Wm + (size_t)(k0 + br) * H_ + n0 + bc * 8);
        }
        CP_COMMIT();
    };

    loadStage(0, 0);
#pragma unroll
    for (int p = 1; p <= NSTAGE - 2; p++)
        if (KT > p) loadStage(p, p);

    for (int kt = 0; kt < KT; kt++) {
        int rem = KT - 1 - kt;
        if (NSTAGE == 4) {
            if (rem >= 2) cp_wait<2>();
            else if (rem == 1) cp_wait<1>();
            else cp_wait<0>();
        } else {
            if (rem >= 1) cp_wait<1>();
            else cp_wait<0>();
        }
        __syncthreads();
        if (kt + NSTAGE - 1 < KT)
            loadStage(kt + NSTAGE - 1, (kt + NSTAGE - 1) % NSTAGE);

        const uint32_t a_base = sbase + (uint32_t)((kt % NSTAGE) * STG_B);
        const uint32_t b_base = a_base + A_STG;
#pragma unroll 2
        for (int ks = 0; ks < KS; ks++) {
            uint32_t a[4][4], bb2[NP][4];
#pragma unroll
            for (int mr = 0; mr < 4; mr++)
                ldm_x4(a[mr], a_base + (warpM * 64 + mr * 16 + lane15) * AS
                                 + ks * 32 + laneHi * 16);
#pragma unroll
            for (int np = 0; np < NP; np++)
                ldm_x4_t(bb2[np], b_base + (ks * 16 + lane15) * 272
                                    + (warpN * TNW + np * 16 + laneHi * 8) * 2);
#pragma unroll
            for (int mr = 0; mr < 4; mr++)
#pragma unroll
                for (int np = 0; np < NP; np++) {
                    mma_f16(c[mr][2 * np + 0], a[mr], bb2[np][0], bb2[np][1]);
                    mma_f16(c[mr][2 * np + 1], a[mr], bb2[np][2], bb2[np][3]);
                }
        }
    }

    __half* xhSide = g_xh + (size_t)side * BS_ * H_;

    // ============== MODE 0: fragment epilogue (reg-sacred shape) ==============
    if (MODE == 0) {
        const int colbase = n0 + warpN * TNW + t4 * 2;
        float* statsDst = g_stats + (size_t)side * BS_ * 2;
#pragma unroll
        for (int mr = 0; mr < 4; mr++) {
#pragma unroll
            for (int hh = 0; hh < 2; hh++) {
                size_t r = m0 + warpM * 64 + mr * 16 + gid + hh * 8;
                __half* xrow = xhSide + r * H_;
                float s = 0.f, sq = 0.f;
#pragma unroll
                for (int nr = 0; nr < NR; nr++) {
                    int col = colbase + nr * 8;
                    float2 bv = *(const float2*)(bias + col);
                    float v0 = fmaxf(c[mr][nr][hh * 2 + 0] + bv.x, 0.f);
                    float v1 = fmaxf(c[mr][nr][hh * 2 + 1] + bv.y, 0.f);
                    *(__half2*)(xrow + col) = __floats2half2_rn(v0, v1);
                    s += v0 + v1;
                    sq += v0 * v0 + v1 * v1;
                }
                s += __shfl_xor_sync(0xffffffffu, s, 1);
                sq += __shfl_xor_sync(0xffffffffu, sq, 1);
                s += __shfl_xor_sync(0xffffffffu, s, 2);
                sq += __shfl_xor_sync(0xffffffffu, sq, 2);
                if (t4 == 0) {
                    atomicAdd(statsDst + r * 2, s);
                    atomicAdd(statsDst + r * 2 + 1, sq);
                }
            }
        }
        return;
    }

    // ============== MODE 1/2: smem-staged, coalesced epilogue ============
    __syncthreads();
    float* sm = (float*)smraw;
#pragma unroll
    for (int mr = 0; mr < 4; mr++)
#pragma unroll
        for (int hh = 0; hh < 2; hh++) {
            int row = warpM * 64 + mr * 16 + gid + hh * 8;
#pragma unroll
            for (int nr = 0; nr < NR; nr++) {
                int col = warpN * TNW + nr * 8 + t4 * 2;
                *(float2*)&sm[row * 132 + col] =
                    make_float2(c[mr][nr][hh * 2 + 0], c[mr][nr][hh * 2 + 1]);
            }
        }
    __syncthreads();

    const int c0 = lane * 4;

    if (MODE == 1) {
        const int cb = (qp_base + side) * H_;
        const float* stats = g_stats + (size_t)(ln_phase + side) * BS_ * 2;
        __half* hSide = g_h + (size_t)side * BS_ * H_;
        const float4 q4 = *(const float4*)(g_q + cb + n0 + c0);
        const float4 p4 = *(const float4*)(g_p + cb + n0 + c0);
        for (int rr = wid; rr < 128; rr += WARPS) {
            size_t r = m0 + rr;
            float4 a4 = *(float4*)&sm[rr * 132 + c0];
            float2 st = *(const float2*)(stats + r * 2);
            float mu = st.x * (1.0f / H_);
            float var = st.y * (1.0f / H_) - mu * mu;
            float rstd = rsqrtf(fmaxf(var, 0.f) + 1e-5f);
            float mt = -rstd * mu;
            float v0 = fmaxf(fmaf(rstd, a4.x, fmaf(mt, q4.x, p4.x)), 0.f);
            float v1 = fmaxf(fmaf(rstd, a4.y, fmaf(mt, q4.y, p4.y)), 0.f);
            float v2 = fmaxf(fmaf(rstd, a4.z, fmaf(mt, q4.z, p4.z)), 0.f);
            float v3 = fmaxf(fmaf(rstd, a4.w, fmaf(mt, q4.w, p4.w)), 0.f);
            __half2 h[2] = {__floats2half2_rn(v0, v1), __floats2half2_rn(v2, v3)};
            *(uint2*)(hSide + r * H_ + n0 + c0) = *(uint2*)h;
        }
        return;
    }

    // MODE 2
    const float4 b4 = *(const float4*)(bias + n0 + c0);
    float* statsDst = (statsPhase >= 0)
        ? g_stats + (size_t)(statsPhase + side) * BS_ * 2 : (float*)0;

    for (int rr = wid; rr < 128; rr += WARPS) {
        size_t r = m0 + rr;
        float4 a4 = *(float4*)&sm[rr * 132 + c0];
        uint2 rh = *(const uint2*)(xhSide + r * H_ + n0 + c0);
        float2 r01 = __half22float2(*(__half2*)&rh.x);
        float2 r23 = __half22float2(*(__half2*)&rh.y);
        float v0 = a4.x + b4.x + r01.x;
        float v1 = a4.y + b4.y + r01.y;
        float v2 = a4.z + b4.z + r23.x;
        float v3 = a4.w + b4.w + r23.y;
        size_t bi = r >> 11, si = r & 2047;
        int ocol = side * H_ + n0 + c0;
        *(float4*)(outA + (si * B_ + bi) * (size_t)(2 * H_) + ocol) =
            make_float4(v0, v1, v2, v3);
        if (outL)
            *(float4*)(outL + (bi * S_ + si) * (size_t)(2 * H_) + ocol) =
                make_float4(v0, v1, v2, v3);
        if (statsDst) {
            __half2 h[2] = {__floats2half2_rn(v0, v1), __floats2half2_rn(v2, v3)};
            *(uint2*)(xhSide + r * H_ + n0 + c0) = *(uint2*)h;
            float s = v0 + v1 + v2 + v3;
            float sq = v0 * v0 + v1 * v1 + v2 * v2 + v3 * v3;
#pragma unroll
            for (int o = 16; o; o >>= 1) {
                s += __shfl_xor_sync(0xffffffffu, s, o);
                sq += __shfl_xor_sync(0xffffffffu, sq, o);
            }
            if (lane == 0) {
                atomicAdd(statsDst + r * 2, s);
                atomicAdd(statsDst + r * 2 + 1, sq);
            }
        }
    }
}

// ---------------------------------------------------------------------------
extern "C" void kernel_launch(void* const* d_in, const int* in_sizes, int n_in,
                              void* d_out, int out_size) {
    const float* inputs = (const float*)d_in[0];
    const float* lp     = (const float*)d_in[1];
    const float* rp     = (const float*)d_in[2];
    const float* Wl     = (const float*)d_in[3];
    const float* bl     = (const float*)d_in[4];
    const float* Wr     = (const float*)d_in[5];
    const float* br     = (const float*)d_in[6];
    const float* lw1    = (const float*)d_in[7];
    const float* lb1    = (const float*)d_in[8];
    const float* lw2    = (const float*)d_in[9];
    const float* lb2    = (const float*)d_in[10];
    const float* lg     = (const float*)d_in[11];
    const float* lbeta  = (const float*)d_in[12];
    const float* rw1    = (const float*)d_in[13];
    const float* rb1    = (const float*)d_in[14];
    const float* rw2    = (const float*)d_in[15];
    const float* rb2    = (const float*)d_in[16];
    const float* rg     = (const float*)d_in[17];
    const float* rbeta  = (const float*)d_in[18];
    float* out = (float*)d_out;
    (void)in_sizes; (void)n_in; (void)out_size;

    const int SMEM0 = 4 * (128 * 80 + 32 * 272);    // 75776
    const int SMEML = 3 * (128 * 144 + 64 * 272);   // 107520
    cudaFuncSetAttribute(tc_gemm<0, 64, 128, 32>,
                         cudaFuncAttributeMaxDynamicSharedMemorySize, SMEM0);
    cudaFuncSetAttribute(tc_gemm<1, 8, 256, 64>,
                         cudaFuncAttributeMaxDynamicSharedMemorySize, SMEML);
    cudaFuncSetAttribute(tc_gemm<2, 8, 256, 64>,
                         cudaFuncAttributeMaxDynamicSharedMemorySize, SMEML);

    // 1) single merged prep: pad + f2h(gamma fold) + q/p + stats zero
    prep_all<<<PAD_BLK + F2H_BLK + QP_BLK + ZERO_BLK, 256>>>(
        inputs, lp, rp, Wl, Wr, lw1, lw2, rw1, rw2,
        lg, rg, lbeta, lb1, rbeta, rb1);

    // 2) wide projections, L+R merged
    tc_gemm<0, 64, 128, 32><<<dim3(4, 16, 32), 128, SMEM0>>>(
        OFF_WL, OFF_WR, bl, br, 0, 0, 0, nullptr, nullptr);

    // 3) residual FF layers, L+R merged
    for (int i = 0; i < L_; i++) {
        bool last = (i == L_ - 1);
        tc_gemm<1, 8, 256, 64><<<dim3(4, 256, 2), 256, SMEML>>>(
            OFF_LW1 + i * 262144, OFF_RW1 + i * 262144,
            nullptr, nullptr,
            i * 2, -1, (i == 0) ? 0 : 2, nullptr, nullptr);

        float* oall = out + (size_t)i * S_ * B_ * 2 * H_;
        float* olast = last ? out + (size_t)L_ * S_ * B_ * 2 * H_ : nullptr;
        tc_gemm<2, 8, 256, 64><<<dim3(4, 256, 2), 256, SMEML>>>(
            OFF_LW2 + i * 262144, OFF_RW2 + i * 262144,
            lb2 + (size_t)i * H_, rb2 + (size_t)i * H_,
            0, last ? -1 : 2, 0, oall, olast);
    }
}